// round 2
// baseline (speedup 1.0000x reference)
#include <cuda_runtime.h>
#include <cstdint>

#define HNUM 8
#define SEQ  4096
#define FIN  512
#define HD   64
#define FOUT 512

__device__ float g_Q[HNUM*SEQ*HD];
__device__ float g_K[HNUM*SEQ*HD];
__device__ float g_V[HNUM*SEQ*HD];
__device__ float g_Hcat[SEQ*HNUM*HD];

__device__ __forceinline__ float to_tf32(float x){
    unsigned u; asm("cvt.rna.tf32.f32 %0,%1;":"=r"(u):"f"(x)); return __uint_as_float(u);
}
__device__ __forceinline__ unsigned fu(float x){ return __float_as_uint(x); }
__device__ __forceinline__ void mma8(float c[4], const unsigned a[4], const unsigned b[2]){
    asm volatile("mma.sync.aligned.m16n8k8.row.col.f32.tf32.tf32.f32 "
        "{%0,%1,%2,%3},{%4,%5,%6,%7},{%8,%9},{%0,%1,%2,%3};\n"
        : "+f"(c[0]),"+f"(c[1]),"+f"(c[2]),"+f"(c[3])
        : "r"(a[0]),"r"(a[1]),"r"(a[2]),"r"(a[3]),"r"(b[0]),"r"(b[1]));
}
__device__ __forceinline__ void split1(float x, float* hi, float* lo){
    float h = to_tf32(x); *hi = h; *lo = to_tf32(x - h);
}

// ---- 64x64 3xTF32 NT GEMM tile: C[64,64] = A[64,K] * B[64,K]^T, 128 threads ----
__device__ __forceinline__ void gemm64(const float* __restrict__ A, int lda,
                                       const float* __restrict__ B, int ldb,
                                       float* __restrict__ C, int ldc, int K)
{
    __shared__ float sAh[64][36], sAl[64][36], sBh[64][36], sBl[64][36];
    const int tid = threadIdx.x, warp = tid>>5, lane = tid&31;
    const int g = lane>>2, q = lane&3;
    const int wm = (warp>>1)*32, wn = (warp&1)*32;
    float Cr[2][4][4];
    #pragma unroll
    for(int mi=0;mi<2;mi++) for(int ni=0;ni<4;ni++) for(int e=0;e<4;e++) Cr[mi][ni][e]=0.f;

    for(int k0=0;k0<K;k0+=32){
        __syncthreads();
        #pragma unroll
        for(int i=0;i<4;i++){
            int idx = tid + 128*i, r = idx>>3, c4 = (idx&7)<<2;
            float4 av = *(const float4*)(A + (size_t)r*lda + k0 + c4);
            float4 bv = *(const float4*)(B + (size_t)r*ldb + k0 + c4);
            split1(av.x,&sAh[r][c4+0],&sAl[r][c4+0]); split1(av.y,&sAh[r][c4+1],&sAl[r][c4+1]);
            split1(av.z,&sAh[r][c4+2],&sAl[r][c4+2]); split1(av.w,&sAh[r][c4+3],&sAl[r][c4+3]);
            split1(bv.x,&sBh[r][c4+0],&sBl[r][c4+0]); split1(bv.y,&sBh[r][c4+1],&sBl[r][c4+1]);
            split1(bv.z,&sBh[r][c4+2],&sBl[r][c4+2]); split1(bv.w,&sBh[r][c4+3],&sBl[r][c4+3]);
        }
        __syncthreads();
        #pragma unroll
        for(int kk=0;kk<32;kk+=8){
            unsigned ah[2][4], al[2][4];
            #pragma unroll
            for(int mi=0;mi<2;mi++){
                int r = wm + mi*16;
                ah[mi][0]=fu(sAh[r+g][kk+q]);   ah[mi][1]=fu(sAh[r+g+8][kk+q]);
                ah[mi][2]=fu(sAh[r+g][kk+q+4]); ah[mi][3]=fu(sAh[r+g+8][kk+q+4]);
                al[mi][0]=fu(sAl[r+g][kk+q]);   al[mi][1]=fu(sAl[r+g+8][kk+q]);
                al[mi][2]=fu(sAl[r+g][kk+q+4]); al[mi][3]=fu(sAl[r+g+8][kk+q+4]);
            }
            #pragma unroll
            for(int ni=0;ni<4;ni++){
                int rn = wn + ni*8 + g;
                unsigned bh[2]={fu(sBh[rn][kk+q]),fu(sBh[rn][kk+q+4])};
                unsigned bl[2]={fu(sBl[rn][kk+q]),fu(sBl[rn][kk+q+4])};
                #pragma unroll
                for(int mi=0;mi<2;mi++){
                    mma8(Cr[mi][ni],ah[mi],bh);
                    mma8(Cr[mi][ni],ah[mi],bl);
                    mma8(Cr[mi][ni],al[mi],bh);
                }
            }
        }
    }
    #pragma unroll
    for(int mi=0;mi<2;mi++) for(int ni=0;ni<4;ni++){
        int row = wm+mi*16+g, col = wn+ni*8+2*q;
        *(float2*)(C + (size_t)row*ldc + col)     = make_float2(Cr[mi][ni][0],Cr[mi][ni][1]);
        *(float2*)(C + (size_t)(row+8)*ldc + col) = make_float2(Cr[mi][ni][2],Cr[mi][ni][3]);
    }
}

__global__ __launch_bounds__(128) void qkv_proj_kernel(const float* __restrict__ X,
    const float* __restrict__ WQ, const float* __restrict__ WK, const float* __restrict__ WV)
{
    int h = blockIdx.z, p = blockIdx.y, m0 = blockIdx.x*64;
    const float* W = (p==0)?WQ:(p==1)?WK:WV;
    float* Cb = (p==0)?g_Q:(p==1)?g_K:g_V;
    gemm64(X + ((size_t)h*SEQ+m0)*FIN, FIN, W + (size_t)h*HD*FIN, FIN,
           Cb + ((size_t)h*SEQ+m0)*HD, HD, FIN);
}

__global__ __launch_bounds__(128) void out_proj_kernel(const float* __restrict__ WO, float* __restrict__ Out)
{
    int m0 = blockIdx.x*64, n0 = blockIdx.y*64;
    gemm64(g_Hcat + (size_t)m0*(HNUM*HD), HNUM*HD, WO + (size_t)n0*(HNUM*HD), HNUM*HD,
           Out + (size_t)m0*FOUT + n0, FOUT, HNUM*HD);
}

// ---------------- flash attention: BM=128, BN=64, 4 warps ----------------
#define QS  68
#define VSD 72
#define SMEM_FLASH (2*128*QS*4 + 2*64*QS*4 + 64*VSD*4 + 128*QS*4 + 128*64)

__global__ __launch_bounds__(128,1) void flash_kernel(const int* __restrict__ mask)
{
    extern __shared__ char smraw[];
    float* Qh = (float*)smraw;           // [128][QS]
    float* Ql = Qh + 128*QS;
    float* Kh = Ql + 128*QS;             // [64][QS]
    float* Kl = Kh + 64*QS;
    float* Vs = Kl + 64*QS;              // [64][VSD]
    float* Ps = Vs + 64*VSD;             // [128][QS]
    unsigned char* Ms = (unsigned char*)(Ps + 128*QS); // [128][64]

    const int h = blockIdx.y, q0 = blockIdx.x*128;
    const int tid = threadIdx.x, warp = tid>>5, lane = tid&31;
    const int g = lane>>2, q = lane&3, r0 = warp*32;

    const float* Qg = g_Q + ((size_t)h*SEQ+q0)*HD;
    const float* Kg = g_K + (size_t)h*SEQ*HD;
    const float* Vg = g_V + (size_t)h*SEQ*HD;
    const int* mg = mask + ((size_t)h*SEQ+q0)*SEQ;

    #pragma unroll
    for(int i=0;i<16;i++){
        int idx = tid+128*i, r = idx>>4, c4 = (idx&15)<<2;
        float4 v = *(const float4*)(Qg + (size_t)r*HD + c4);
        split1(v.x*0.125f,&Qh[r*QS+c4+0],&Ql[r*QS+c4+0]);
        split1(v.y*0.125f,&Qh[r*QS+c4+1],&Ql[r*QS+c4+1]);
        split1(v.z*0.125f,&Qh[r*QS+c4+2],&Ql[r*QS+c4+2]);
        split1(v.w*0.125f,&Qh[r*QS+c4+3],&Ql[r*QS+c4+3]);
    }

    float mr[2][2], lr[2][2], O[2][8][4];
    #pragma unroll
    for(int mi=0;mi<2;mi++) for(int hh=0;hh<2;hh++){ mr[mi][hh]=-1e30f; lr[mi][hh]=0.f; }
    #pragma unroll
    for(int mi=0;mi<2;mi++) for(int nt=0;nt<8;nt++) for(int e=0;e<4;e++) O[mi][nt][e]=0.f;

    for(int kt=0;kt<SEQ/64;kt++){
        const int k0 = kt*64;
        __syncthreads();
        #pragma unroll
        for(int i=0;i<8;i++){
            int idx = tid+128*i, r = idx>>4, c4 = (idx&15)<<2;
            float4 kv = *(const float4*)(Kg + (size_t)(k0+r)*HD + c4);
            float4 vv = *(const float4*)(Vg + (size_t)(k0+r)*HD + c4);
            split1(kv.x,&Kh[r*QS+c4+0],&Kl[r*QS+c4+0]); split1(kv.y,&Kh[r*QS+c4+1],&Kl[r*QS+c4+1]);
            split1(kv.z,&Kh[r*QS+c4+2],&Kl[r*QS+c4+2]); split1(kv.w,&Kh[r*QS+c4+3],&Kl[r*QS+c4+3]);
            Vs[r*VSD+c4+0]=to_tf32(vv.x); Vs[r*VSD+c4+1]=to_tf32(vv.y);
            Vs[r*VSD+c4+2]=to_tf32(vv.z); Vs[r*VSD+c4+3]=to_tf32(vv.w);
        }
        #pragma unroll
        for(int i=0;i<16;i++){
            int idx = tid+128*i, r = idx>>4, c4 = (idx&15)<<2;
            int4 mv = *(const int4*)(mg + (size_t)r*SEQ + k0 + c4);
            unsigned pk = (mv.x?1u:0u)|((mv.y?1u:0u)<<8)|((mv.z?1u:0u)<<16)|((mv.w?1u:0u)<<24);
            *(unsigned*)(Ms + r*64 + c4) = pk;
        }
        __syncthreads();

        float S[2][8][4];
        #pragma unroll
        for(int mi=0;mi<2;mi++) for(int nt=0;nt<8;nt++) for(int e=0;e<4;e++) S[mi][nt][e]=0.f;
        #pragma unroll
        for(int kk=0;kk<64;kk+=8){
            unsigned ah[2][4], al[2][4];
            #pragma unroll
            for(int mi=0;mi<2;mi++){
                int r = r0+mi*16;
                ah[mi][0]=fu(Qh[(r+g)*QS+kk+q]);   ah[mi][1]=fu(Qh[(r+g+8)*QS+kk+q]);
                ah[mi][2]=fu(Qh[(r+g)*QS+kk+q+4]); ah[mi][3]=fu(Qh[(r+g+8)*QS+kk+q+4]);
                al[mi][0]=fu(Ql[(r+g)*QS+kk+q]);   al[mi][1]=fu(Ql[(r+g+8)*QS+kk+q]);
                al[mi][2]=fu(Ql[(r+g)*QS+kk+q+4]); al[mi][3]=fu(Ql[(r+g+8)*QS+kk+q+4]);
            }
            #pragma unroll
            for(int nt=0;nt<8;nt++){
                int rn = nt*8+g;
                unsigned bh[2]={fu(Kh[rn*QS+kk+q]),fu(Kh[rn*QS+kk+q+4])};
                unsigned bl[2]={fu(Kl[rn*QS+kk+q]),fu(Kl[rn*QS+kk+q+4])};
                #pragma unroll
                for(int mi=0;mi<2;mi++){
                    mma8(S[mi][nt],ah[mi],bh);
                    mma8(S[mi][nt],ah[mi],bl);
                    mma8(S[mi][nt],al[mi],bh);
                }
            }
        }
        #pragma unroll
        for(int mi=0;mi<2;mi++){
            int rA = r0+mi*16+g, rB = rA+8;
            float tmax[2]={-1e30f,-1e30f};
            #pragma unroll
            for(int nt=0;nt<8;nt++){
                int col = nt*8+2*q;
                if(!Ms[rA*64+col])   S[mi][nt][0]=-1e30f;
                if(!Ms[rA*64+col+1]) S[mi][nt][1]=-1e30f;
                if(!Ms[rB*64+col])   S[mi][nt][2]=-1e30f;
                if(!Ms[rB*64+col+1]) S[mi][nt][3]=-1e30f;
                tmax[0]=fmaxf(tmax[0],fmaxf(S[mi][nt][0],S[mi][nt][1]));
                tmax[1]=fmaxf(tmax[1],fmaxf(S[mi][nt][2],S[mi][nt][3]));
            }
            #pragma unroll
            for(int off=1;off<4;off<<=1){
                tmax[0]=fmaxf(tmax[0],__shfl_xor_sync(0xffffffffu,tmax[0],off));
                tmax[1]=fmaxf(tmax[1],__shfl_xor_sync(0xffffffffu,tmax[1],off));
            }
            #pragma unroll
            for(int hh=0;hh<2;hh++){
                float mnew = fmaxf(mr[mi][hh], tmax[hh]);
                float corr = __expf(mr[mi][hh]-mnew);
                mr[mi][hh]=mnew; lr[mi][hh]*=corr;
                #pragma unroll
                for(int nt=0;nt<8;nt++){ O[mi][nt][2*hh]*=corr; O[mi][nt][2*hh+1]*=corr; }
            }
            float ts[2]={0.f,0.f};
            #pragma unroll
            for(int nt=0;nt<8;nt++){
                S[mi][nt][0]=__expf(S[mi][nt][0]-mr[mi][0]);
                S[mi][nt][1]=__expf(S[mi][nt][1]-mr[mi][0]);
                S[mi][nt][2]=__expf(S[mi][nt][2]-mr[mi][1]);
                S[mi][nt][3]=__expf(S[mi][nt][3]-mr[mi][1]);
                ts[0]+=S[mi][nt][0]+S[mi][nt][1];
                ts[1]+=S[mi][nt][2]+S[mi][nt][3];
            }
            #pragma unroll
            for(int off=1;off<4;off<<=1){
                ts[0]+=__shfl_xor_sync(0xffffffffu,ts[0],off);
                ts[1]+=__shfl_xor_sync(0xffffffffu,ts[1],off);
            }
            lr[mi][0]+=ts[0]; lr[mi][1]+=ts[1];
            #pragma unroll
            for(int nt=0;nt<8;nt++){
                int col = nt*8+2*q;
                Ps[rA*QS+col]=to_tf32(S[mi][nt][0]); Ps[rA*QS+col+1]=to_tf32(S[mi][nt][1]);
                Ps[rB*QS+col]=to_tf32(S[mi][nt][2]); Ps[rB*QS+col+1]=to_tf32(S[mi][nt][3]);
            }
        }
        __syncwarp();
        #pragma unroll
        for(int kk=0;kk<64;kk+=8){
            unsigned a[2][4];
            #pragma unroll
            for(int mi=0;mi<2;mi++){
                int r = r0+mi*16;
                a[mi][0]=fu(Ps[(r+g)*QS+kk+q]);   a[mi][1]=fu(Ps[(r+g+8)*QS+kk+q]);
                a[mi][2]=fu(Ps[(r+g)*QS+kk+q+4]); a[mi][3]=fu(Ps[(r+g+8)*QS+kk+q+4]);
            }
            #pragma unroll
            for(int nt=0;nt<8;nt++){
                unsigned b[2]={fu(Vs[(kk+q)*VSD+nt*8+g]),fu(Vs[(kk+q+4)*VSD+nt*8+g])};
                #pragma unroll
                for(int mi=0;mi<2;mi++) mma8(O[mi][nt],a[mi],b);
            }
        }
        __syncwarp();
    }
    #pragma unroll
    for(int mi=0;mi<2;mi++) for(int hh=0;hh<2;hh++){
        float inv = 1.f/lr[mi][hh];
        int row = q0 + r0 + mi*16 + g + hh*8;
        float* out = g_Hcat + (size_t)row*(HNUM*HD) + h*HD;
        #pragma unroll
        for(int nt=0;nt<8;nt++){
            int col = nt*8+2*q;
            out[col]   = O[mi][nt][2*hh]*inv;
            out[col+1] = O[mi][nt][2*hh+1]*inv;
        }
    }
}

extern "C" void kernel_launch(void* const* d_in, const int* in_sizes, int n_in,
                              void* d_out, int out_size)
{
    const float* X  = (const float*)d_in[0];
    const int* mask = (const int*)d_in[1];
    const float* WQ = (const float*)d_in[2];
    const float* WK = (const float*)d_in[3];
    const float* WV = (const float*)d_in[4];
    const float* WO = (const float*)d_in[5];
    float* out = (float*)d_out;

    cudaFuncSetAttribute(flash_kernel, cudaFuncAttributeMaxDynamicSharedMemorySize, SMEM_FLASH);

    qkv_proj_kernel<<<dim3(64,3,8),128>>>(X,WQ,WK,WV);
    flash_kernel<<<dim3(32,8),128,SMEM_FLASH>>>(mask);
    out_proj_kernel<<<dim3(64,8),128>>>(WO,out);
}

// round 3
// speedup vs baseline: 1.1088x; 1.1088x over previous
#include <cuda_runtime.h>
#include <cstdint>

#define HNUM 8
#define SEQ  4096
#define FIN  512
#define HD   64
#define FOUT 512

__device__ float g_Q[HNUM*SEQ*HD];
__device__ float g_K[HNUM*SEQ*HD];
__device__ float g_V[HNUM*SEQ*HD];
__device__ float g_Hcat[SEQ*HNUM*HD];

__device__ __forceinline__ float to_tf32(float x){
    unsigned u; asm("cvt.rna.tf32.f32 %0,%1;":"=r"(u):"f"(x)); return __uint_as_float(u);
}
__device__ __forceinline__ unsigned fu(float x){ return __float_as_uint(x); }
__device__ __forceinline__ void mma8(float c[4], const unsigned a[4], const unsigned b[2]){
    asm volatile("mma.sync.aligned.m16n8k8.row.col.f32.tf32.tf32.f32 "
        "{%0,%1,%2,%3},{%4,%5,%6,%7},{%8,%9},{%0,%1,%2,%3};\n"
        : "+f"(c[0]),"+f"(c[1]),"+f"(c[2]),"+f"(c[3])
        : "r"(a[0]),"r"(a[1]),"r"(a[2]),"r"(a[3]),"r"(b[0]),"r"(b[1]));
}
__device__ __forceinline__ void split1(float x, float* hi, float* lo){
    float h = to_tf32(x); *hi = h; *lo = to_tf32(x - h);
}
__device__ __forceinline__ void cpa16(void* s, const void* g){
    unsigned sa = (unsigned)__cvta_generic_to_shared(s);
    asm volatile("cp.async.cg.shared.global [%0],[%1],16;\n" :: "r"(sa),"l"(g));
}
#define CP_COMMIT() asm volatile("cp.async.commit_group;\n")
#define CP_WAIT1()  asm volatile("cp.async.wait_group 1;\n")
#define CP_WAIT0()  asm volatile("cp.async.wait_group 0;\n")

// ---- 64x64 3xTF32 NT GEMM tile: C[64,64] = A[64,K] * B[64,K]^T, 128 threads ----
__device__ __forceinline__ void gemm64(const float* __restrict__ A, int lda,
                                       const float* __restrict__ B, int ldb,
                                       float* __restrict__ C, int ldc, int K)
{
    __shared__ float sAh[64][36], sAl[64][36], sBh[64][36], sBl[64][36];
    const int tid = threadIdx.x, warp = tid>>5, lane = tid&31;
    const int g = lane>>2, q = lane&3;
    const int wm = (warp>>1)*32, wn = (warp&1)*32;
    float Cr[2][4][4];
    #pragma unroll
    for(int mi=0;mi<2;mi++) for(int ni=0;ni<4;ni++) for(int e=0;e<4;e++) Cr[mi][ni][e]=0.f;

    for(int k0=0;k0<K;k0+=32){
        __syncthreads();
        #pragma unroll
        for(int i=0;i<4;i++){
            int idx = tid + 128*i, r = idx>>3, c4 = (idx&7)<<2;
            float4 av = *(const float4*)(A + (size_t)r*lda + k0 + c4);
            float4 bv = *(const float4*)(B + (size_t)r*ldb + k0 + c4);
            split1(av.x,&sAh[r][c4+0],&sAl[r][c4+0]); split1(av.y,&sAh[r][c4+1],&sAl[r][c4+1]);
            split1(av.z,&sAh[r][c4+2],&sAl[r][c4+2]); split1(av.w,&sAh[r][c4+3],&sAl[r][c4+3]);
            split1(bv.x,&sBh[r][c4+0],&sBl[r][c4+0]); split1(bv.y,&sBh[r][c4+1],&sBl[r][c4+1]);
            split1(bv.z,&sBh[r][c4+2],&sBl[r][c4+2]); split1(bv.w,&sBh[r][c4+3],&sBl[r][c4+3]);
        }
        __syncthreads();
        #pragma unroll
        for(int kk=0;kk<32;kk+=8){
            unsigned ah[2][4], al[2][4];
            #pragma unroll
            for(int mi=0;mi<2;mi++){
                int r = wm + mi*16;
                ah[mi][0]=fu(sAh[r+g][kk+q]);   ah[mi][1]=fu(sAh[r+g+8][kk+q]);
                ah[mi][2]=fu(sAh[r+g][kk+q+4]); ah[mi][3]=fu(sAh[r+g+8][kk+q+4]);
                al[mi][0]=fu(sAl[r+g][kk+q]);   al[mi][1]=fu(sAl[r+g+8][kk+q]);
                al[mi][2]=fu(sAl[r+g][kk+q+4]); al[mi][3]=fu(sAl[r+g+8][kk+q+4]);
            }
            #pragma unroll
            for(int ni=0;ni<4;ni++){
                int rn = wn + ni*8 + g;
                unsigned bh[2]={fu(sBh[rn][kk+q]),fu(sBh[rn][kk+q+4])};
                unsigned bl[2]={fu(sBl[rn][kk+q]),fu(sBl[rn][kk+q+4])};
                #pragma unroll
                for(int mi=0;mi<2;mi++){
                    mma8(Cr[mi][ni],ah[mi],bh);
                    mma8(Cr[mi][ni],ah[mi],bl);
                    mma8(Cr[mi][ni],al[mi],bh);
                }
            }
        }
    }
    #pragma unroll
    for(int mi=0;mi<2;mi++) for(int ni=0;ni<4;ni++){
        int row = wm+mi*16+g, col = wn+ni*8+2*q;
        *(float2*)(C + (size_t)row*ldc + col)     = make_float2(Cr[mi][ni][0],Cr[mi][ni][1]);
        *(float2*)(C + (size_t)(row+8)*ldc + col) = make_float2(Cr[mi][ni][2],Cr[mi][ni][3]);
    }
}

__global__ __launch_bounds__(128) void qkv_proj_kernel(const float* __restrict__ X,
    const float* __restrict__ WQ, const float* __restrict__ WK, const float* __restrict__ WV)
{
    int h = blockIdx.z, p = blockIdx.y, m0 = blockIdx.x*64;
    const float* W = (p==0)?WQ:(p==1)?WK:WV;
    float* Cb = (p==0)?g_Q:(p==1)?g_K:g_V;
    gemm64(X + ((size_t)h*SEQ+m0)*FIN, FIN, W + (size_t)h*HD*FIN, FIN,
           Cb + ((size_t)h*SEQ+m0)*HD, HD, FIN);
}

__global__ __launch_bounds__(128) void out_proj_kernel(const float* __restrict__ WO, float* __restrict__ Out)
{
    int m0 = blockIdx.x*64, n0 = blockIdx.y*64;
    gemm64(g_Hcat + (size_t)m0*(HNUM*HD), HNUM*HD, WO + (size_t)n0*(HNUM*HD), HNUM*HD,
           Out + (size_t)m0*FOUT + n0, FOUT, HNUM*HD);
}

// ------------- flash attention v2: BM=128, BN=64, 8 warps, cp.async pipeline -------------
#define QSTR 68
#define VSTR 72
// floats: Q 128*68 ; K 2*64*68 ; V 2*64*72 ; mask(int) 2*128*68
#define SMEM_FLASH ((128*QSTR + 2*64*QSTR + 2*64*VSTR + 2*128*QSTR)*4)

__global__ __launch_bounds__(256,1) void flash_kernel(const int* __restrict__ mask)
{
    extern __shared__ char smraw[];
    float* Qs = (float*)smraw;               // [128][68] raw (pre-scaled)
    float* Ks = Qs + 128*QSTR;               // [2][64][68] raw
    float* Vs = Ks + 2*64*QSTR;              // [2][64][72] raw
    int*   Mi = (int*)(Vs + 2*64*VSTR);      // [2][128][68] raw int

    const int h = blockIdx.y, q0 = blockIdx.x*128;
    const int tid = threadIdx.x, warp = tid>>5, lane = tid&31;
    const int g = lane>>2, q = lane&3, r0 = warp*16;
    const int srcA = (lane & ~3) | (q>>1);
    const bool odd = (q&1);

    const float* Qg = g_Q + ((size_t)h*SEQ+q0)*HD;
    const float* Kg = g_K + (size_t)h*SEQ*HD;
    const float* Vg = g_V + (size_t)h*SEQ*HD;
    const int*   mg = mask + ((size_t)h*SEQ+q0)*SEQ;

    // stage Q once, raw, pre-scaled by 1/sqrt(64)
    #pragma unroll
    for(int i=0;i<8;i++){
        int idx = tid+256*i, r = idx>>4, c4 = (idx&15)<<2;
        float4 v = *(const float4*)(Qg + (size_t)r*HD + c4);
        float* d = Qs + r*QSTR + c4;
        d[0]=v.x*0.125f; d[1]=v.y*0.125f; d[2]=v.z*0.125f; d[3]=v.w*0.125f;
    }

    // async stage of tile kt into buffer b
    auto stage = [&](int b, int kt){
        const int k0 = kt*64;
        float* kd = Ks + b*64*QSTR;
        float* vd = Vs + b*64*VSTR;
        int*   md = Mi + b*128*QSTR;
        #pragma unroll
        for(int i=0;i<4;i++){
            int idx = tid+256*i, r = idx>>4, c = (idx&15)<<2;
            cpa16(kd + r*QSTR + c, Kg + (size_t)(k0+r)*HD + c);
            cpa16(vd + r*VSTR + c, Vg + (size_t)(k0+r)*HD + c);
        }
        #pragma unroll
        for(int i=0;i<8;i++){
            int idx = tid+256*i, r = idx>>4, c = (idx&15)<<2;
            cpa16(md + r*QSTR + c, mg + (size_t)r*SEQ + k0 + c);
        }
    };

    stage(0,0); CP_COMMIT();

    float mr[2]={-1e30f,-1e30f}, lr[2]={0.f,0.f};
    float O[8][4];
    #pragma unroll
    for(int nt=0;nt<8;nt++) for(int e=0;e<4;e++) O[nt][e]=0.f;

    for(int kt=0;kt<SEQ/64;kt++){
        const int buf = kt&1;
        if(kt < SEQ/64-1){ stage(buf^1, kt+1); CP_COMMIT(); CP_WAIT1(); }
        else { CP_WAIT0(); }
        __syncthreads();

        const float* kb = Ks + buf*64*QSTR;
        const float* vb = Vs + buf*64*VSTR;
        const int*   mb = Mi + buf*128*QSTR;

        // ---- S = Qscaled * K^T (3xTF32) ----
        float S[8][4];
        #pragma unroll
        for(int nt=0;nt<8;nt++) for(int e=0;e<4;e++) S[nt][e]=0.f;
        #pragma unroll
        for(int kk=0;kk<64;kk+=8){
            float qa[4];
            qa[0]=Qs[(r0+g)*QSTR+kk+q];   qa[1]=Qs[(r0+8+g)*QSTR+kk+q];
            qa[2]=Qs[(r0+g)*QSTR+kk+q+4]; qa[3]=Qs[(r0+8+g)*QSTR+kk+q+4];
            unsigned ah[4], al[4];
            #pragma unroll
            for(int e=0;e<4;e++){
                float hi = to_tf32(qa[e]);
                ah[e]=fu(hi); al[e]=fu(to_tf32(qa[e]-hi));
            }
            #pragma unroll
            for(int nt=0;nt<8;nt++){
                float b0 = kb[(nt*8+g)*QSTR+kk+q];
                float b1 = kb[(nt*8+g)*QSTR+kk+q+4];
                float h0 = to_tf32(b0), h1 = to_tf32(b1);
                unsigned bh[2]={fu(h0),fu(h1)};
                unsigned bl[2]={fu(to_tf32(b0-h0)),fu(to_tf32(b1-h1))};
                mma8(S[nt],ah,bh);
                mma8(S[nt],ah,bl);
                mma8(S[nt],al,bh);
            }
        }

        // ---- mask + online softmax ----
        const int rA = r0+g, rB = r0+8+g;
        float tmax[2]={-1e30f,-1e30f};
        #pragma unroll
        for(int nt=0;nt<8;nt++){
            int col = nt*8+2*q;
            int2 mA = *(const int2*)(mb + rA*QSTR + col);
            int2 mB = *(const int2*)(mb + rB*QSTR + col);
            if(!mA.x) S[nt][0]=-1e30f;
            if(!mA.y) S[nt][1]=-1e30f;
            if(!mB.x) S[nt][2]=-1e30f;
            if(!mB.y) S[nt][3]=-1e30f;
            tmax[0]=fmaxf(tmax[0],fmaxf(S[nt][0],S[nt][1]));
            tmax[1]=fmaxf(tmax[1],fmaxf(S[nt][2],S[nt][3]));
        }
        #pragma unroll
        for(int off=1;off<4;off<<=1){
            tmax[0]=fmaxf(tmax[0],__shfl_xor_sync(0xffffffffu,tmax[0],off));
            tmax[1]=fmaxf(tmax[1],__shfl_xor_sync(0xffffffffu,tmax[1],off));
        }
        #pragma unroll
        for(int hh=0;hh<2;hh++){
            float mnew = fmaxf(mr[hh], tmax[hh]);
            float corr = __expf(mr[hh]-mnew);
            mr[hh]=mnew; lr[hh]*=corr;
            #pragma unroll
            for(int nt=0;nt<8;nt++){ O[nt][2*hh]*=corr; O[nt][2*hh+1]*=corr; }
        }
        float ts[2]={0.f,0.f};
        #pragma unroll
        for(int nt=0;nt<8;nt++){
            S[nt][0]=__expf(S[nt][0]-mr[0]);
            S[nt][1]=__expf(S[nt][1]-mr[0]);
            S[nt][2]=__expf(S[nt][2]-mr[1]);
            S[nt][3]=__expf(S[nt][3]-mr[1]);
            ts[0]+=S[nt][0]+S[nt][1];
            ts[1]+=S[nt][2]+S[nt][3];
            S[nt][0]=to_tf32(S[nt][0]); S[nt][1]=to_tf32(S[nt][1]);
            S[nt][2]=to_tf32(S[nt][2]); S[nt][3]=to_tf32(S[nt][3]);
        }
        #pragma unroll
        for(int off=1;off<4;off<<=1){
            ts[0]+=__shfl_xor_sync(0xffffffffu,ts[0],off);
            ts[1]+=__shfl_xor_sync(0xffffffffu,ts[1],off);
        }
        lr[0]+=ts[0]; lr[1]+=ts[1];

        // ---- O += P * V (C-frag -> A-frag via shuffle; no smem round trip) ----
        #pragma unroll
        for(int j=0;j<8;j++){
            float p0 = __shfl_sync(0xffffffffu, S[j][0], srcA);
            float p1 = __shfl_sync(0xffffffffu, S[j][1], srcA);
            float p2 = __shfl_sync(0xffffffffu, S[j][2], srcA);
            float p3 = __shfl_sync(0xffffffffu, S[j][3], srcA);
            float u0 = __shfl_sync(0xffffffffu, S[j][0], srcA+2);
            float u1 = __shfl_sync(0xffffffffu, S[j][1], srcA+2);
            float u2 = __shfl_sync(0xffffffffu, S[j][2], srcA+2);
            float u3 = __shfl_sync(0xffffffffu, S[j][3], srcA+2);
            unsigned a[4];
            a[0]=fu(odd?p1:p0); a[1]=fu(odd?p3:p2);
            a[2]=fu(odd?u1:u0); a[3]=fu(odd?u3:u2);
            #pragma unroll
            for(int nt=0;nt<8;nt++){
                float v0 = vb[(8*j+q)*VSTR + nt*8+g];
                float v1 = vb[(8*j+q+4)*VSTR + nt*8+g];
                unsigned bb[2]={fu(to_tf32(v0)),fu(to_tf32(v1))};
                mma8(O[nt],a,bb);
            }
        }
        __syncthreads();
    }

    // ---- epilogue ----
    #pragma unroll
    for(int hh=0;hh<2;hh++){
        float inv = 1.f/lr[hh];
        int row = q0 + r0 + hh*8 + g;
        float* out = g_Hcat + (size_t)row*(HNUM*HD) + h*HD;
        #pragma unroll
        for(int nt=0;nt<8;nt++){
            int col = nt*8+2*q;
            out[col]   = O[nt][2*hh]*inv;
            out[col+1] = O[nt][2*hh+1]*inv;
        }
    }
}

extern "C" void kernel_launch(void* const* d_in, const int* in_sizes, int n_in,
                              void* d_out, int out_size)
{
    const float* X  = (const float*)d_in[0];
    const int* mask = (const int*)d_in[1];
    const float* WQ = (const float*)d_in[2];
    const float* WK = (const float*)d_in[3];
    const float* WV = (const float*)d_in[4];
    const float* WO = (const float*)d_in[5];
    float* out = (float*)d_out;

    cudaFuncSetAttribute(flash_kernel, cudaFuncAttributeMaxDynamicSharedMemorySize, SMEM_FLASH);

    qkv_proj_kernel<<<dim3(64,3,8),128>>>(X,WQ,WK,WV);
    flash_kernel<<<dim3(32,8),256,SMEM_FLASH>>>(mask);
    out_proj_kernel<<<dim3(64,8),128>>>(WO,out);
}

// round 4
// speedup vs baseline: 1.1391x; 1.0273x over previous
#include <cuda_runtime.h>
#include <cstdint>

#define HNUM 8
#define SEQ  4096
#define FIN  512
#define HD   64
#define FOUT 512

__device__ float g_Q[HNUM*SEQ*HD];
__device__ float g_K[HNUM*SEQ*HD];
__device__ float g_V[HNUM*SEQ*HD];
__device__ float g_Hcat[SEQ*HNUM*HD];

__device__ __forceinline__ float to_tf32(float x){
    unsigned u; asm("cvt.rna.tf32.f32 %0,%1;":"=r"(u):"f"(x)); return __uint_as_float(u);
}
__device__ __forceinline__ unsigned fu(float x){ return __float_as_uint(x); }
__device__ __forceinline__ void mma8(float c[4], const unsigned a[4], const unsigned b[2]){
    asm volatile("mma.sync.aligned.m16n8k8.row.col.f32.tf32.tf32.f32 "
        "{%0,%1,%2,%3},{%4,%5,%6,%7},{%8,%9},{%0,%1,%2,%3};\n"
        : "+f"(c[0]),"+f"(c[1]),"+f"(c[2]),"+f"(c[3])
        : "r"(a[0]),"r"(a[1]),"r"(a[2]),"r"(a[3]),"r"(b[0]),"r"(b[1]));
}
__device__ __forceinline__ void split1(float x, float* hi, float* lo){
    float h = to_tf32(x); *hi = h; *lo = to_tf32(x - h);
}
__device__ __forceinline__ void cpa16(void* s, const void* g){
    unsigned sa = (unsigned)__cvta_generic_to_shared(s);
    asm volatile("cp.async.cg.shared.global [%0],[%1],16;\n" :: "r"(sa),"l"(g));
}
#define CP_COMMIT() asm volatile("cp.async.commit_group;\n")
#define CP_WAIT1()  asm volatile("cp.async.wait_group 1;\n")
#define CP_WAIT0()  asm volatile("cp.async.wait_group 0;\n")

// ---- 64x64 3xTF32 NT GEMM tile: C[64,64] = A[64,K] * B[64,K]^T, 128 threads ----
__device__ __forceinline__ void gemm64(const float* __restrict__ A, int lda,
                                       const float* __restrict__ B, int ldb,
                                       float* __restrict__ C, int ldc, int K)
{
    __shared__ float sAh[64][36], sAl[64][36], sBh[64][36], sBl[64][36];
    const int tid = threadIdx.x, warp = tid>>5, lane = tid&31;
    const int g = lane>>2, q = lane&3;
    const int wm = (warp>>1)*32, wn = (warp&1)*32;
    float Cr[2][4][4];
    #pragma unroll
    for(int mi=0;mi<2;mi++) for(int ni=0;ni<4;ni++) for(int e=0;e<4;e++) Cr[mi][ni][e]=0.f;

    for(int k0=0;k0<K;k0+=32){
        __syncthreads();
        #pragma unroll
        for(int i=0;i<4;i++){
            int idx = tid + 128*i, r = idx>>3, c4 = (idx&7)<<2;
            float4 av = *(const float4*)(A + (size_t)r*lda + k0 + c4);
            float4 bv = *(const float4*)(B + (size_t)r*ldb + k0 + c4);
            split1(av.x,&sAh[r][c4+0],&sAl[r][c4+0]); split1(av.y,&sAh[r][c4+1],&sAl[r][c4+1]);
            split1(av.z,&sAh[r][c4+2],&sAl[r][c4+2]); split1(av.w,&sAh[r][c4+3],&sAl[r][c4+3]);
            split1(bv.x,&sBh[r][c4+0],&sBl[r][c4+0]); split1(bv.y,&sBh[r][c4+1],&sBl[r][c4+1]);
            split1(bv.z,&sBh[r][c4+2],&sBl[r][c4+2]); split1(bv.w,&sBh[r][c4+3],&sBl[r][c4+3]);
        }
        __syncthreads();
        #pragma unroll
        for(int kk=0;kk<32;kk+=8){
            unsigned ah[2][4], al[2][4];
            #pragma unroll
            for(int mi=0;mi<2;mi++){
                int r = wm + mi*16;
                ah[mi][0]=fu(sAh[r+g][kk+q]);   ah[mi][1]=fu(sAh[r+g+8][kk+q]);
                ah[mi][2]=fu(sAh[r+g][kk+q+4]); ah[mi][3]=fu(sAh[r+g+8][kk+q+4]);
                al[mi][0]=fu(sAl[r+g][kk+q]);   al[mi][1]=fu(sAl[r+g+8][kk+q]);
                al[mi][2]=fu(sAl[r+g][kk+q+4]); al[mi][3]=fu(sAl[r+g+8][kk+q+4]);
            }
            #pragma unroll
            for(int ni=0;ni<4;ni++){
                int rn = wn + ni*8 + g;
                unsigned bh[2]={fu(sBh[rn][kk+q]),fu(sBh[rn][kk+q+4])};
                unsigned bl[2]={fu(sBl[rn][kk+q]),fu(sBl[rn][kk+q+4])};
                #pragma unroll
                for(int mi=0;mi<2;mi++){
                    mma8(Cr[mi][ni],ah[mi],bh);
                    mma8(Cr[mi][ni],ah[mi],bl);
                    mma8(Cr[mi][ni],al[mi],bh);
                }
            }
        }
    }
    #pragma unroll
    for(int mi=0;mi<2;mi++) for(int ni=0;ni<4;ni++){
        int row = wm+mi*16+g, col = wn+ni*8+2*q;
        *(float2*)(C + (size_t)row*ldc + col)     = make_float2(Cr[mi][ni][0],Cr[mi][ni][1]);
        *(float2*)(C + (size_t)(row+8)*ldc + col) = make_float2(Cr[mi][ni][2],Cr[mi][ni][3]);
    }
}

__global__ __launch_bounds__(128) void qkv_proj_kernel(const float* __restrict__ X,
    const float* __restrict__ WQ, const float* __restrict__ WK, const float* __restrict__ WV)
{
    int h = blockIdx.z, p = blockIdx.y, m0 = blockIdx.x*64;
    const float* W = (p==0)?WQ:(p==1)?WK:WV;
    float* Cb = (p==0)?g_Q:(p==1)?g_K:g_V;
    gemm64(X + ((size_t)h*SEQ+m0)*FIN, FIN, W + (size_t)h*HD*FIN, FIN,
           Cb + ((size_t)h*SEQ+m0)*HD, HD, FIN);
}

__global__ __launch_bounds__(128) void out_proj_kernel(const float* __restrict__ WO, float* __restrict__ Out)
{
    int m0 = blockIdx.x*64, n0 = blockIdx.y*64;
    gemm64(g_Hcat + (size_t)m0*(HNUM*HD), HNUM*HD, WO + (size_t)n0*(HNUM*HD), HNUM*HD,
           Out + (size_t)m0*FOUT + n0, FOUT, HNUM*HD);
}

// ------------- flash v3: BM=256, BN=64, 16 warps, single wave, cp.async -------------
#define QSTR 68
#define VSTR 72
#define NT   (SEQ/64)
// floats: Q 256*68 ; K 2*64*68 ; V 2*64*72 ; mask(int, single buf) 256*68
#define SMEM_FLASH ((256*QSTR + 2*64*QSTR + 2*64*VSTR + 256*QSTR)*4)

__global__ __launch_bounds__(512,1) void flash_kernel(const int* __restrict__ mask)
{
    extern __shared__ char smraw[];
    float* Qs = (float*)smraw;               // [256][68] raw (pre-scaled)
    float* Ks = Qs + 256*QSTR;               // [2][64][68]
    float* Vs = Ks + 2*64*QSTR;              // [2][64][72]
    int*   Mi = (int*)(Vs + 2*64*VSTR);      // [256][68] single-buffer

    const int h = blockIdx.y, q0 = blockIdx.x*256;
    const int tid = threadIdx.x, warp = tid>>5, lane = tid&31;
    const int g = lane>>2, q = lane&3, r0 = warp*16;
    const int srcA = (lane & ~3) | (q>>1);
    const bool odd = (q&1);

    const float* Qg = g_Q + ((size_t)h*SEQ+q0)*HD;
    const float* Kg = g_K + (size_t)h*SEQ*HD;
    const float* Vg = g_V + (size_t)h*SEQ*HD;
    const int*   mg = mask + ((size_t)h*SEQ+q0)*SEQ;

    // stage Q once, raw, pre-scaled by 1/sqrt(64)
    #pragma unroll
    for(int i=0;i<8;i++){
        int idx = tid+512*i, r = idx>>4, c4 = (idx&15)<<2;
        float4 v = *(const float4*)(Qg + (size_t)r*HD + c4);
        float* d = Qs + r*QSTR + c4;
        d[0]=v.x*0.125f; d[1]=v.y*0.125f; d[2]=v.z*0.125f; d[3]=v.w*0.125f;
    }

    auto stageKV = [&](int b, int kt){
        const int k0 = kt*64;
        float* kd = Ks + b*64*QSTR;
        float* vd = Vs + b*64*VSTR;
        #pragma unroll
        for(int i=0;i<2;i++){
            int idx = tid+512*i, r = idx>>4, c = (idx&15)<<2;
            cpa16(kd + r*QSTR + c, Kg + (size_t)(k0+r)*HD + c);
            cpa16(vd + r*VSTR + c, Vg + (size_t)(k0+r)*HD + c);
        }
    };
    auto stageM = [&](int kt){
        const int k0 = kt*64;
        #pragma unroll
        for(int i=0;i<8;i++){
            int idx = tid+512*i, r = idx>>4, c = (idx&15)<<2;
            cpa16(Mi + r*QSTR + c, mg + (size_t)r*SEQ + k0 + c);
        }
    };

    stageKV(0,0); CP_COMMIT();
    stageM(0);    CP_COMMIT();

    float mr[2]={-1e30f,-1e30f}, lr[2]={0.f,0.f};
    float O[8][4];
    #pragma unroll
    for(int nt=0;nt<8;nt++) for(int e=0;e<4;e++) O[nt][e]=0.f;

    for(int kt=0;kt<NT;kt++){
        const int buf = kt&1;
        if(kt < NT-1){ stageKV(buf^1, kt+1); CP_COMMIT(); CP_WAIT1(); }
        else { CP_WAIT0(); }
        __syncthreads();

        const float* kb = Ks + buf*64*QSTR;
        const float* vb = Vs + buf*64*VSTR;

        // ---- S = Qscaled * K^T (3xTF32) ----
        float S[8][4];
        #pragma unroll
        for(int nt=0;nt<8;nt++) for(int e=0;e<4;e++) S[nt][e]=0.f;
        #pragma unroll
        for(int kk=0;kk<64;kk+=8){
            float qa[4];
            qa[0]=Qs[(r0+g)*QSTR+kk+q];   qa[1]=Qs[(r0+8+g)*QSTR+kk+q];
            qa[2]=Qs[(r0+g)*QSTR+kk+q+4]; qa[3]=Qs[(r0+8+g)*QSTR+kk+q+4];
            unsigned ah[4], al[4];
            #pragma unroll
            for(int e=0;e<4;e++){
                float hi = to_tf32(qa[e]);
                ah[e]=fu(hi); al[e]=fu(to_tf32(qa[e]-hi));
            }
            #pragma unroll
            for(int nt=0;nt<8;nt++){
                float b0 = kb[(nt*8+g)*QSTR+kk+q];
                float b1 = kb[(nt*8+g)*QSTR+kk+q+4];
                float h0 = to_tf32(b0), h1 = to_tf32(b1);
                unsigned bh[2]={fu(h0),fu(h1)};
                unsigned bl[2]={fu(to_tf32(b0-h0)),fu(to_tf32(b1-h1))};
                mma8(S[nt],ah,bh);
                mma8(S[nt],ah,bl);
                mma8(S[nt],al,bh);
            }
        }

        // ---- mask + online softmax ----
        const int rA = r0+g, rB = r0+8+g;
        float tmax[2]={-1e30f,-1e30f};
        #pragma unroll
        for(int nt=0;nt<8;nt++){
            int col = nt*8+2*q;
            int2 mA = *(const int2*)(Mi + rA*QSTR + col);
            int2 mB = *(const int2*)(Mi + rB*QSTR + col);
            if(!mA.x) S[nt][0]=-1e30f;
            if(!mA.y) S[nt][1]=-1e30f;
            if(!mB.x) S[nt][2]=-1e30f;
            if(!mB.y) S[nt][3]=-1e30f;
            tmax[0]=fmaxf(tmax[0],fmaxf(S[nt][0],S[nt][1]));
            tmax[1]=fmaxf(tmax[1],fmaxf(S[nt][2],S[nt][3]));
        }
        #pragma unroll
        for(int off=1;off<4;off<<=1){
            tmax[0]=fmaxf(tmax[0],__shfl_xor_sync(0xffffffffu,tmax[0],off));
            tmax[1]=fmaxf(tmax[1],__shfl_xor_sync(0xffffffffu,tmax[1],off));
        }
        #pragma unroll
        for(int hh=0;hh<2;hh++){
            float mnew = fmaxf(mr[hh], tmax[hh]);
            float corr = __expf(mr[hh]-mnew);
            mr[hh]=mnew; lr[hh]*=corr;
            #pragma unroll
            for(int nt=0;nt<8;nt++){ O[nt][2*hh]*=corr; O[nt][2*hh+1]*=corr; }
        }
        float ts[2]={0.f,0.f};
        #pragma unroll
        for(int nt=0;nt<8;nt++){
            S[nt][0]=__expf(S[nt][0]-mr[0]);
            S[nt][1]=__expf(S[nt][1]-mr[0]);
            S[nt][2]=__expf(S[nt][2]-mr[1]);
            S[nt][3]=__expf(S[nt][3]-mr[1]);
            ts[0]+=S[nt][0]+S[nt][1];
            ts[1]+=S[nt][2]+S[nt][3];
            S[nt][0]=to_tf32(S[nt][0]); S[nt][1]=to_tf32(S[nt][1]);
            S[nt][2]=to_tf32(S[nt][2]); S[nt][3]=to_tf32(S[nt][3]);
        }
        #pragma unroll
        for(int off=1;off<4;off<<=1){
            ts[0]+=__shfl_xor_sync(0xffffffffu,ts[0],off);
            ts[1]+=__shfl_xor_sync(0xffffffffu,ts[1],off);
        }
        lr[0]+=ts[0]; lr[1]+=ts[1];

        // mask fully consumed -> safe to restage after barrier
        __syncthreads();
        if(kt < NT-1){ stageM(kt+1); CP_COMMIT(); }

        // ---- O += P * V (C-frag -> A-frag via shuffle) ----
        #pragma unroll
        for(int j=0;j<8;j++){
            float p0 = __shfl_sync(0xffffffffu, S[j][0], srcA);
            float p1 = __shfl_sync(0xffffffffu, S[j][1], srcA);
            float p2 = __shfl_sync(0xffffffffu, S[j][2], srcA);
            float p3 = __shfl_sync(0xffffffffu, S[j][3], srcA);
            float u0 = __shfl_sync(0xffffffffu, S[j][0], srcA+2);
            float u1 = __shfl_sync(0xffffffffu, S[j][1], srcA+2);
            float u2 = __shfl_sync(0xffffffffu, S[j][2], srcA+2);
            float u3 = __shfl_sync(0xffffffffu, S[j][3], srcA+2);
            unsigned a[4];
            a[0]=fu(odd?p1:p0); a[1]=fu(odd?p3:p2);
            a[2]=fu(odd?u1:u0); a[3]=fu(odd?u3:u2);
            #pragma unroll
            for(int nt=0;nt<8;nt++){
                float v0 = vb[(8*j+q)*VSTR + nt*8+g];
                float v1 = vb[(8*j+q+4)*VSTR + nt*8+g];
                unsigned bb[2]={fu(to_tf32(v0)),fu(to_tf32(v1))};
                mma8(O[nt],a,bb);
            }
        }
        __syncthreads();
    }

    // ---- epilogue ----
    #pragma unroll
    for(int hh=0;hh<2;hh++){
        float inv = 1.f/lr[hh];
        int row = q0 + r0 + hh*8 + g;
        float* out = g_Hcat + (size_t)row*(HNUM*HD) + h*HD;
        #pragma unroll
        for(int nt=0;nt<8;nt++){
            int col = nt*8+2*q;
            out[col]   = O[nt][2*hh]*inv;
            out[col+1] = O[nt][2*hh+1]*inv;
        }
    }
}

extern "C" void kernel_launch(void* const* d_in, const int* in_sizes, int n_in,
                              void* d_out, int out_size)
{
    const float* X  = (const float*)d_in[0];
    const int* mask = (const int*)d_in[1];
    const float* WQ = (const float*)d_in[2];
    const float* WK = (const float*)d_in[3];
    const float* WV = (const float*)d_in[4];
    const float* WO = (const float*)d_in[5];
    float* out = (float*)d_out;

    cudaFuncSetAttribute(flash_kernel, cudaFuncAttributeMaxDynamicSharedMemorySize, SMEM_FLASH);

    qkv_proj_kernel<<<dim3(64,3,8),128>>>(X,WQ,WK,WV);
    flash_kernel<<<dim3(16,8),512,SMEM_FLASH>>>(mask);
    out_proj_kernel<<<dim3(64,8),128>>>(WO,out);
}

// round 8
// speedup vs baseline: 1.7608x; 1.5458x over previous
#include <cuda_runtime.h>
#include <cuda_bf16.h>
#include <cstdint>

#define HNUM 8
#define SEQ  4096
#define FIN  512
#define HD   64
#define FOUT 512
#define S_SCALE 0.18033688011112042f  /* 0.125 * log2(e) */

__device__ float g_Q[HNUM*SEQ*HD];
__device__ float g_K[HNUM*SEQ*HD];
__device__ float g_V[HNUM*SEQ*HD];
__device__ float g_Hcat[SEQ*HNUM*HD];
__device__ __nv_bfloat16 g_Qh[HNUM*SEQ*HD], g_Ql[HNUM*SEQ*HD];
__device__ __nv_bfloat16 g_Kh[HNUM*SEQ*HD], g_Kl[HNUM*SEQ*HD];
__device__ __nv_bfloat16 g_Vh[HNUM*SEQ*HD], g_Vl[HNUM*SEQ*HD];

__device__ __forceinline__ float to_tf32(float x){
    unsigned u; asm("cvt.rna.tf32.f32 %0,%1;":"=r"(u):"f"(x)); return __uint_as_float(u);
}
__device__ __forceinline__ unsigned fu(float x){ return __float_as_uint(x); }
__device__ __forceinline__ void mma8(float c[4], const unsigned a[4], const unsigned b[2]){
    asm volatile("mma.sync.aligned.m16n8k8.row.col.f32.tf32.tf32.f32 "
        "{%0,%1,%2,%3},{%4,%5,%6,%7},{%8,%9},{%0,%1,%2,%3};\n"
        : "+f"(c[0]),"+f"(c[1]),"+f"(c[2]),"+f"(c[3])
        : "r"(a[0]),"r"(a[1]),"r"(a[2]),"r"(a[3]),"r"(b[0]),"r"(b[1]));
}
__device__ __forceinline__ void split1(float x, float* hi, float* lo){
    float h = to_tf32(x); *hi = h; *lo = to_tf32(x - h);
}
__device__ __forceinline__ void cpa16s(uint32_t sa, const void* g){
    asm volatile("cp.async.cg.shared.global [%0],[%1],16;\n" :: "r"(sa),"l"(g));
}
#define CP_COMMIT() asm volatile("cp.async.commit_group;\n")
#define CP_WAIT0()  asm volatile("cp.async.wait_group 0;\n" ::: "memory")

__device__ __forceinline__ uint32_t smem_u32(const void* p){
    uint32_t a; asm("{ .reg .u64 t; cvta.to.shared.u64 t, %1; cvt.u32.u64 %0, t; }" : "=r"(a) : "l"(p));
    return a;
}
__device__ __forceinline__ void ldsm4(uint32_t r[4], uint32_t a){
    asm volatile("ldmatrix.sync.aligned.m8n8.x4.shared.b16 {%0,%1,%2,%3},[%4];"
        : "=r"(r[0]),"=r"(r[1]),"=r"(r[2]),"=r"(r[3]) : "r"(a));
}
__device__ __forceinline__ void ldsm4t(uint32_t r[4], uint32_t a){
    asm volatile("ldmatrix.sync.aligned.m8n8.x4.trans.shared.b16 {%0,%1,%2,%3},[%4];"
        : "=r"(r[0]),"=r"(r[1]),"=r"(r[2]),"=r"(r[3]) : "r"(a));
}
__device__ __forceinline__ void mma16(float c[4], const uint32_t a[4], const uint32_t b[2]){
    asm volatile("mma.sync.aligned.m16n8k16.row.col.f32.bf16.bf16.f32 "
        "{%0,%1,%2,%3},{%4,%5,%6,%7},{%8,%9},{%0,%1,%2,%3};\n"
        : "+f"(c[0]),"+f"(c[1]),"+f"(c[2]),"+f"(c[3])
        : "r"(a[0]),"r"(a[1]),"r"(a[2]),"r"(a[3]),"r"(b[0]),"r"(b[1]));
}
__device__ __forceinline__ uint32_t packbf(float hi, float lo){
    uint32_t d; asm("cvt.rn.bf16x2.f32 %0,%1,%2;" : "=r"(d) : "f"(hi), "f"(lo)); return d;
}

// ======================= projection GEMMs (unchanged, known-good) =======================
__device__ __forceinline__ void gemm64(const float* __restrict__ A, int lda,
                                       const float* __restrict__ B, int ldb,
                                       float* __restrict__ C, int ldc, int K)
{
    __shared__ float sAh[64][36], sAl[64][36], sBh[64][36], sBl[64][36];
    const int tid = threadIdx.x, warp = tid>>5, lane = tid&31;
    const int g = lane>>2, q = lane&3;
    const int wm = (warp>>1)*32, wn = (warp&1)*32;
    float Cr[2][4][4];
    #pragma unroll
    for(int mi=0;mi<2;mi++) for(int ni=0;ni<4;ni++) for(int e=0;e<4;e++) Cr[mi][ni][e]=0.f;

    for(int k0=0;k0<K;k0+=32){
        __syncthreads();
        #pragma unroll
        for(int i=0;i<4;i++){
            int idx = tid + 128*i, r = idx>>3, c4 = (idx&7)<<2;
            float4 av = *(const float4*)(A + (size_t)r*lda + k0 + c4);
            float4 bv = *(const float4*)(B + (size_t)r*ldb + k0 + c4);
            split1(av.x,&sAh[r][c4+0],&sAl[r][c4+0]); split1(av.y,&sAh[r][c4+1],&sAl[r][c4+1]);
            split1(av.z,&sAh[r][c4+2],&sAl[r][c4+2]); split1(av.w,&sAh[r][c4+3],&sAl[r][c4+3]);
            split1(bv.x,&sBh[r][c4+0],&sBl[r][c4+0]); split1(bv.y,&sBh[r][c4+1],&sBl[r][c4+1]);
            split1(bv.z,&sBh[r][c4+2],&sBl[r][c4+2]); split1(bv.w,&sBh[r][c4+3],&sBl[r][c4+3]);
        }
        __syncthreads();
        #pragma unroll
        for(int kk=0;kk<32;kk+=8){
            unsigned ah[2][4], al[2][4];
            #pragma unroll
            for(int mi=0;mi<2;mi++){
                int r = wm + mi*16;
                ah[mi][0]=fu(sAh[r+g][kk+q]);   ah[mi][1]=fu(sAh[r+g+8][kk+q]);
                ah[mi][2]=fu(sAh[r+g][kk+q+4]); ah[mi][3]=fu(sAh[r+g+8][kk+q+4]);
                al[mi][0]=fu(sAl[r+g][kk+q]);   al[mi][1]=fu(sAl[r+g+8][kk+q]);
                al[mi][2]=fu(sAl[r+g][kk+q+4]); al[mi][3]=fu(sAl[r+g+8][kk+q+4]);
            }
            #pragma unroll
            for(int ni=0;ni<4;ni++){
                int rn = wn + ni*8 + g;
                unsigned bh[2]={fu(sBh[rn][kk+q]),fu(sBh[rn][kk+q+4])};
                unsigned bl[2]={fu(sBl[rn][kk+q]),fu(sBl[rn][kk+q+4])};
                #pragma unroll
                for(int mi=0;mi<2;mi++){
                    mma8(Cr[mi][ni],ah[mi],bh);
                    mma8(Cr[mi][ni],ah[mi],bl);
                    mma8(Cr[mi][ni],al[mi],bh);
                }
            }
        }
    }
    #pragma unroll
    for(int mi=0;mi<2;mi++) for(int ni=0;ni<4;ni++){
        int row = wm+mi*16+g, col = wn+ni*8+2*q;
        *(float2*)(C + (size_t)row*ldc + col)     = make_float2(Cr[mi][ni][0],Cr[mi][ni][1]);
        *(float2*)(C + (size_t)(row+8)*ldc + col) = make_float2(Cr[mi][ni][2],Cr[mi][ni][3]);
    }
}

__global__ __launch_bounds__(128) void qkv_proj_kernel(const float* __restrict__ X,
    const float* __restrict__ WQ, const float* __restrict__ WK, const float* __restrict__ WV)
{
    int h = blockIdx.z, p = blockIdx.y, m0 = blockIdx.x*64;
    const float* W = (p==0)?WQ:(p==1)?WK:WV;
    float* Cb = (p==0)?g_Q:(p==1)?g_K:g_V;
    gemm64(X + ((size_t)h*SEQ+m0)*FIN, FIN, W + (size_t)h*HD*FIN, FIN,
           Cb + ((size_t)h*SEQ+m0)*HD, HD, FIN);
}

__global__ __launch_bounds__(128) void out_proj_kernel(const float* __restrict__ WO, float* __restrict__ Out)
{
    int m0 = blockIdx.x*64, n0 = blockIdx.y*64;
    gemm64(g_Hcat + (size_t)m0*(HNUM*HD), HNUM*HD, WO + (size_t)n0*(HNUM*HD), HNUM*HD,
           Out + (size_t)m0*FOUT + n0, FOUT, HNUM*HD);
}

// ======================= fp32 -> bf16 hi/lo split =======================
__global__ __launch_bounds__(256) void split_kernel()
{
    size_t i = ((size_t)blockIdx.x*256 + threadIdx.x)*4;
    float4 qv = *(const float4*)(g_Q+i);
    float4 kv = *(const float4*)(g_K+i);
    float4 vv = *(const float4*)(g_V+i);
    qv.x*=S_SCALE; qv.y*=S_SCALE; qv.z*=S_SCALE; qv.w*=S_SCALE;
    float e[4];
    auto wr = [&](__nv_bfloat16* H, __nv_bfloat16* L, float4 t){
        e[0]=t.x; e[1]=t.y; e[2]=t.z; e[3]=t.w;
        __nv_bfloat16 h[4], l[4];
        #pragma unroll
        for(int j=0;j<4;j++){
            h[j] = __float2bfloat16(e[j]);
            l[j] = __float2bfloat16(e[j] - __bfloat162float(h[j]));
        }
        __nv_bfloat162 p0, p1; p0.x=h[0]; p0.y=h[1]; p1.x=h[2]; p1.y=h[3];
        *(__nv_bfloat162*)(H+i) = p0; *(__nv_bfloat162*)(H+i+2) = p1;
        p0.x=l[0]; p0.y=l[1]; p1.x=l[2]; p1.y=l[3];
        *(__nv_bfloat162*)(L+i) = p0; *(__nv_bfloat162*)(L+i+2) = p1;
    };
    wr(g_Qh, g_Ql, qv);
    wr(g_Kh, g_Kl, kv);
    wr(g_Vh, g_Vl, vv);
}

// ======================= bf16 flash: BM=256, BN=64, 16 warps =======================
#define NT (SEQ/64)
#define OFF_QH 0
#define OFF_QL 32768
#define OFF_K  65536      /* [2 buf][Kh 8192 | Kl 8192] */
#define OFF_V  98304      /* [2 buf][Vh 8192 | Vl 8192] */
#define OFF_M  131072     /* int [256][68] */
#define SMEM_FLASH 200704

__global__ __launch_bounds__(512,1) void flash_bf16_kernel(const int* __restrict__ mask)
{
    extern __shared__ char sm[];
    const uint32_t smb = smem_u32(sm);
    const int tid = threadIdx.x, warp = tid>>5, lane = tid&31;
    const int g = lane>>2, q = lane&3, r0 = warp*16;
    const int h = blockIdx.y, q0 = blockIdx.x*256;

    const __nv_bfloat16* Qhg = g_Qh + ((size_t)h*SEQ+q0)*HD;
    const __nv_bfloat16* Qlg = g_Ql + ((size_t)h*SEQ+q0)*HD;
    const __nv_bfloat16* Khg = g_Kh + (size_t)h*SEQ*HD;
    const __nv_bfloat16* Klg = g_Kl + (size_t)h*SEQ*HD;
    const __nv_bfloat16* Vhg = g_Vh + (size_t)h*SEQ*HD;
    const __nv_bfloat16* Vlg = g_Vl + (size_t)h*SEQ*HD;
    const int* mg = mask + ((size_t)h*SEQ+q0)*SEQ;
    int* Mi = (int*)(sm + OFF_M);

    // ldmatrix lane->address mappings
    const int a_row = (lane&7) + (lane&8);        // A & V(trans) mats: r+0,r+8 by lane&8
    const int a_c16 = (lane>>4)&1;                //                    col+16B by lane&16
    const int b_row = (lane&7) + ((lane&16)>>1);  // B(K) mats: r+8 by lane&16
    const int b_c16 = (lane>>3)&1;                //            col+16B by lane&8
    const uint32_t a_swz = (uint32_t)(lane&7)<<4;

    // ---- stage Q (bf16 hi/lo, swizzled) ----
    #pragma unroll
    for(int i=0;i<8;i++){
        int idx = tid+512*i, half = idx>>11, t = idx&2047, r = t>>3, s = t&7;
        const __nv_bfloat16* src = (half? Qlg:Qhg) + (size_t)r*HD + s*8;
        cpa16s(smb + (half?OFF_QL:OFF_QH) + r*128 + ((s*16)^((r&7)<<4)), src);
    }
    auto stageKV = [&](int kt){
        const int k0 = kt*64, buf = kt&1;
        #pragma unroll
        for(int i=0;i<4;i++){
            int idx = tid+512*i, tens = idx>>9, t = idx&511, r = t>>3, s = t&7;
            const __nv_bfloat16* sp = (tens==0)?Khg:(tens==1)?Klg:(tens==2)?Vhg:Vlg;
            uint32_t db = (tens<2 ? OFF_K : OFF_V) + buf*16384 + (tens&1)*8192;
            cpa16s(smb + db + r*128 + ((s*16)^((r&7)<<4)), sp + (size_t)(k0+r)*HD + s*8);
        }
    };
    auto stageM = [&](int kt){
        const int k0 = kt*64;
        #pragma unroll
        for(int i=0;i<8;i++){
            int idx = tid+512*i, r = idx>>4, s = idx&15;
            cpa16s(smb + OFF_M + (r*68 + s*4)*4, mg + (size_t)r*SEQ + k0 + s*4);
        }
    };
    stageKV(0); stageM(0); CP_COMMIT();

    float mr[2]={-1e30f,-1e30f}, lr[2]={0.f,0.f};
    float O[8][4];
    #pragma unroll
    for(int nt=0;nt<8;nt++) for(int e=0;e<4;e++) O[nt][e]=0.f;

    for(int kt=0;kt<NT;kt++){
        const int buf = kt&1;
        CP_WAIT0();
        __syncthreads();
        if(kt+1<NT){ stageKV(kt+1); CP_COMMIT(); }

        // ---- S = Q K^T (bf16 3-product) ----
        float S[8][4];
        #pragma unroll
        for(int nt=0;nt<8;nt++) for(int e=0;e<4;e++) S[nt][e]=0.f;
        #pragma unroll
        for(int kk4=0;kk4<4;kk4++){
            const uint32_t kkb = kk4*32;
            uint32_t ah[4], al[4];
            uint32_t qa = smb + OFF_QH + (r0+a_row)*128 + ((kkb + a_c16*16) ^ a_swz);
            ldsm4(ah, qa);
            ldsm4(al, qa + (OFF_QL-OFF_QH));
            #pragma unroll
            for(int ntp=0;ntp<4;ntp++){
                const int n0 = ntp*16;
                uint32_t bh[4], bl[4];
                uint32_t ka = smb + OFF_K + buf*16384 + (n0+b_row)*128 + ((kkb + b_c16*16) ^ ((uint32_t)(b_row&7)<<4));
                ldsm4(bh, ka);
                ldsm4(bl, ka + 8192);
                mma16(S[2*ntp],   ah, &bh[0]); mma16(S[2*ntp],   ah, &bl[0]); mma16(S[2*ntp],   al, &bh[0]);
                mma16(S[2*ntp+1], ah, &bh[2]); mma16(S[2*ntp+1], ah, &bl[2]); mma16(S[2*ntp+1], al, &bh[2]);
            }
        }

        // ---- mask + online softmax (exp2 domain) ----
        const int rA = r0+g, rB = r0+8+g;
        float tmax[2]={-1e30f,-1e30f};
        #pragma unroll
        for(int nt=0;nt<8;nt++){
            int col = nt*8+2*q;
            int2 mA = *(const int2*)(Mi + rA*68 + col);
            int2 mB = *(const int2*)(Mi + rB*68 + col);
            if(!mA.x) S[nt][0]=-1e30f;
            if(!mA.y) S[nt][1]=-1e30f;
            if(!mB.x) S[nt][2]=-1e30f;
            if(!mB.y) S[nt][3]=-1e30f;
            tmax[0]=fmaxf(tmax[0],fmaxf(S[nt][0],S[nt][1]));
            tmax[1]=fmaxf(tmax[1],fmaxf(S[nt][2],S[nt][3]));
        }
        #pragma unroll
        for(int off=1;off<4;off<<=1){
            tmax[0]=fmaxf(tmax[0],__shfl_xor_sync(0xffffffffu,tmax[0],off));
            tmax[1]=fmaxf(tmax[1],__shfl_xor_sync(0xffffffffu,tmax[1],off));
        }
        float corr[2];
        #pragma unroll
        for(int hh=0;hh<2;hh++){
            float mnew = fmaxf(mr[hh], tmax[hh]);
            asm("ex2.approx.ftz.f32 %0,%1;" : "=f"(corr[hh]) : "f"(mr[hh]-mnew));
            mr[hh]=mnew; lr[hh]*=corr[hh];
            #pragma unroll
            for(int nt=0;nt<8;nt++){ O[nt][2*hh]*=corr[hh]; O[nt][2*hh+1]*=corr[hh]; }
        }
        float ts[2]={0.f,0.f};
        #pragma unroll
        for(int nt=0;nt<8;nt++){
            #pragma unroll
            for(int e=0;e<4;e++){
                float v; asm("ex2.approx.ftz.f32 %0,%1;" : "=f"(v) : "f"(S[nt][e]-mr[e>>1]));
                S[nt][e]=v; ts[e>>1]+=v;
            }
        }
        #pragma unroll
        for(int off=1;off<4;off<<=1){
            ts[0]+=__shfl_xor_sync(0xffffffffu,ts[0],off);
            ts[1]+=__shfl_xor_sync(0xffffffffu,ts[1],off);
        }
        lr[0]+=ts[0]; lr[1]+=ts[1];

        __syncthreads();                       // Mi fully consumed
        if(kt+1<NT){ stageM(kt+1); CP_COMMIT(); }

        // ---- P (bf16x2 pack; C-frag layout == A-frag layout) ----
        uint32_t P[8][2];
        #pragma unroll
        for(int nt=0;nt<8;nt++){
            P[nt][0] = packbf(S[nt][1], S[nt][0]);
            P[nt][1] = packbf(S[nt][3], S[nt][2]);
        }
        // ---- O += P V (V hi+lo) ----
        #pragma unroll
        for(int ktp=0;ktp<4;ktp++){
            uint32_t a[4] = { P[2*ktp][0], P[2*ktp][1], P[2*ktp+1][0], P[2*ktp+1][1] };
            #pragma unroll
            for(int np=0;np<4;np++){
                const int n0 = np*16;
                uint32_t vh[4], vl[4];
                uint32_t va = smb + OFF_V + buf*16384 + (ktp*16 + a_row)*128 + ((n0*2 + a_c16*16) ^ a_swz);
                ldsm4t(vh, va);
                ldsm4t(vl, va + 8192);
                mma16(O[2*np],   a, &vh[0]); mma16(O[2*np],   a, &vl[0]);
                mma16(O[2*np+1], a, &vh[2]); mma16(O[2*np+1], a, &vl[2]);
            }
        }
    }

    // ---- epilogue ----
    #pragma unroll
    for(int hh=0;hh<2;hh++){
        float inv = 1.f/lr[hh];
        int row = q0 + r0 + hh*8 + g;
        float* out = g_Hcat + (size_t)row*(HNUM*HD) + h*HD;
        #pragma unroll
        for(int nt=0;nt<8;nt++){
            int col = nt*8+2*q;
            out[col]   = O[nt][2*hh]*inv;
            out[col+1] = O[nt][2*hh+1]*inv;
        }
    }
}

extern "C" void kernel_launch(void* const* d_in, const int* in_sizes, int n_in,
                              void* d_out, int out_size)
{
    const float* X  = (const float*)d_in[0];
    const int* mask = (const int*)d_in[1];
    const float* WQ = (const float*)d_in[2];
    const float* WK = (const float*)d_in[3];
    const float* WV = (const float*)d_in[4];
    const float* WO = (const float*)d_in[5];
    float* out = (float*)d_out;

    cudaFuncSetAttribute(flash_bf16_kernel, cudaFuncAttributeMaxDynamicSharedMemorySize, SMEM_FLASH);

    qkv_proj_kernel<<<dim3(64,3,8),128>>>(X,WQ,WK,WV);
    split_kernel<<<2048,256>>>();
    flash_bf16_kernel<<<dim3(16,8),512,SMEM_FLASH>>>(mask);
    out_proj_kernel<<<dim3(64,8),128>>>(WO,out);
}

// round 9
// speedup vs baseline: 1.8854x; 1.0708x over previous
#include <cuda_runtime.h>
#include <cuda_bf16.h>
#include <cstdint>

#define HNUM 8
#define SEQ  4096
#define FIN  512
#define HD   64
#define FOUT 512
#define S_SCALE 0.18033688011112042f  /* 0.125 * log2(e) */
typedef __nv_bfloat16 bf;

// bf16 split planes
__device__ bf g_X0[HNUM*SEQ*FIN], g_X1[HNUM*SEQ*FIN], g_X2[HNUM*SEQ*FIN];
__device__ bf g_W0[4][HNUM*HD*FIN], g_W1[4][HNUM*HD*FIN], g_W2[4][HNUM*HD*FIN];
__device__ bf g_Qh[HNUM*SEQ*HD], g_Ql[HNUM*SEQ*HD];
__device__ bf g_Kh[HNUM*SEQ*HD], g_Kl[HNUM*SEQ*HD];
__device__ bf g_Vh[HNUM*SEQ*HD], g_Vl[HNUM*SEQ*HD];
__device__ bf g_H0[SEQ*FOUT], g_H1[SEQ*FOUT], g_H2[SEQ*FOUT];

__device__ __forceinline__ uint32_t packbf(float hi, float lo){
    uint32_t d; asm("cvt.rn.bf16x2.f32 %0,%1,%2;" : "=r"(d) : "f"(hi), "f"(lo)); return d;
}
__device__ __forceinline__ void split3p(float v0, float v1, uint32_t& p0, uint32_t& p1, uint32_t& p2){
    p0 = packbf(v1, v0);
    float a0 = v0 - __uint_as_float(p0<<16);
    float a1 = v1 - __uint_as_float(p0 & 0xFFFF0000u);
    p1 = packbf(a1, a0);
    float b0 = a0 - __uint_as_float(p1<<16);
    float b1 = a1 - __uint_as_float(p1 & 0xFFFF0000u);
    p2 = packbf(b1, b0);
}
__device__ __forceinline__ void split2p(float v0, float v1, uint32_t& p0, uint32_t& p1){
    p0 = packbf(v1, v0);
    p1 = packbf(v1 - __uint_as_float(p0 & 0xFFFF0000u), v0 - __uint_as_float(p0<<16));
}
__device__ __forceinline__ void cpa16s(uint32_t sa, const void* g){
    asm volatile("cp.async.cg.shared.global [%0],[%1],16;\n" :: "r"(sa),"l"(g));
}
#define CP_COMMIT() asm volatile("cp.async.commit_group;\n")
#define CP_WAIT0()  asm volatile("cp.async.wait_group 0;\n" ::: "memory")
__device__ __forceinline__ uint32_t smem_u32(const void* p){
    uint32_t a; asm("{ .reg .u64 t; cvta.to.shared.u64 t, %1; cvt.u32.u64 %0, t; }" : "=r"(a) : "l"(p));
    return a;
}
__device__ __forceinline__ void ldsm4(uint32_t r[4], uint32_t a){
    asm volatile("ldmatrix.sync.aligned.m8n8.x4.shared.b16 {%0,%1,%2,%3},[%4];"
        : "=r"(r[0]),"=r"(r[1]),"=r"(r[2]),"=r"(r[3]) : "r"(a));
}
__device__ __forceinline__ void ldsm4t(uint32_t r[4], uint32_t a){
    asm volatile("ldmatrix.sync.aligned.m8n8.x4.trans.shared.b16 {%0,%1,%2,%3},[%4];"
        : "=r"(r[0]),"=r"(r[1]),"=r"(r[2]),"=r"(r[3]) : "r"(a));
}
__device__ __forceinline__ void mma16(float c[4], const uint32_t a[4], const uint32_t b[2]){
    asm volatile("mma.sync.aligned.m16n8k16.row.col.f32.bf16.bf16.f32 "
        "{%0,%1,%2,%3},{%4,%5,%6,%7},{%8,%9},{%0,%1,%2,%3};\n"
        : "+f"(c[0]),"+f"(c[1]),"+f"(c[2]),"+f"(c[3])
        : "r"(a[0]),"r"(a[1]),"r"(a[2]),"r"(a[3]),"r"(b[0]),"r"(b[1]));
}

// ===================== split kernels =====================
__global__ __launch_bounds__(256) void splitX_kernel(const float* __restrict__ X)
{
    size_t i = ((size_t)blockIdx.x*256 + threadIdx.x)*4;
    float4 v = *(const float4*)(X+i);
    uint32_t a0,a1,a2,b0,b1,b2;
    split3p(v.x,v.y,a0,a1,a2); split3p(v.z,v.w,b0,b1,b2);
    *(uint32_t*)(g_X0+i)=a0; *(uint32_t*)(g_X0+i+2)=b0;
    *(uint32_t*)(g_X1+i)=a1; *(uint32_t*)(g_X1+i+2)=b1;
    *(uint32_t*)(g_X2+i)=a2; *(uint32_t*)(g_X2+i+2)=b2;
}
__global__ __launch_bounds__(256) void splitW_kernel(const float* __restrict__ WQ,
    const float* __restrict__ WK, const float* __restrict__ WV, const float* __restrict__ WO)
{
    int m = blockIdx.y;
    const float* src = (m==0)?WQ:(m==1)?WK:(m==2)?WV:WO;
    size_t i = ((size_t)blockIdx.x*256 + threadIdx.x)*4;
    float4 v = *(const float4*)(src+i);
    uint32_t a0,a1,a2,b0,b1,b2;
    split3p(v.x,v.y,a0,a1,a2); split3p(v.z,v.w,b0,b1,b2);
    *(uint32_t*)(g_W0[m]+i)=a0; *(uint32_t*)(g_W0[m]+i+2)=b0;
    *(uint32_t*)(g_W1[m]+i)=a1; *(uint32_t*)(g_W1[m]+i+2)=b1;
    *(uint32_t*)(g_W2[m]+i)=a2; *(uint32_t*)(g_W2[m]+i+2)=b2;
}

// ===================== bf16 6-product GEMM core =====================
// C[64,64] = A[64,K]*B[64,K]^T ; A/B pre-split into 3 bf16 planes; 128 threads.
#define GP_SM 49152
__device__ __forceinline__ void gemm_bf_main(
    const bf* A0,const bf* A1,const bf* A2,int lda,
    const bf* B0,const bf* B1,const bf* B2,int ldb,
    int K, float Cr[2][4][4], char* sm)
{
    const uint32_t smb = smem_u32(sm);
    const int tid = threadIdx.x, warp = tid>>5, lane = tid&31;
    const int wm = (warp>>1)*32, wn = (warp&1)*32;
    const int a_row = (lane&7) + (lane&8);
    const int a_c16 = (lane>>4)&1;
    const int b_row = (lane&7) + ((lane&16)>>1);
    const int b_c16 = (lane>>3)&1;
    const bf* Ap[3] = {A0,A1,A2};
    const bf* Bp[3] = {B0,B1,B2};
    const int PA[6] = {0,0,1,1,0,2};
    const int PB[6] = {0,1,0,1,2,0};

    for(int k0=0;k0<K;k0+=64){
        __syncthreads();
        #pragma unroll
        for(int i=0;i<12;i++){
            int idx = tid+128*i, p = idx>>9, t = idx&511, r = t>>3, s = t&7;
            uint32_t off = p*8192 + r*128 + ((s*16)^((r&7)<<4));
            cpa16s(smb + off, Ap[p] + (size_t)r*lda + k0 + s*8);
            cpa16s(smb + 24576 + off, Bp[p] + (size_t)r*ldb + k0 + s*8);
        }
        CP_COMMIT(); CP_WAIT0();
        __syncthreads();
        #pragma unroll
        for(int k16=0;k16<4;k16++){
            uint32_t aF[3][2][4], bF[3][2][4];
            #pragma unroll
            for(int p=0;p<3;p++){
                #pragma unroll
                for(int mi=0;mi<2;mi++)
                    ldsm4(aF[p][mi], smb + p*8192 + (wm+mi*16+a_row)*128 + ((k16*32 + a_c16*16)^((a_row&7)<<4)));
                #pragma unroll
                for(int nj=0;nj<2;nj++)
                    ldsm4(bF[p][nj], smb + 24576 + p*8192 + (wn+nj*16+b_row)*128 + ((k16*32 + b_c16*16)^((b_row&7)<<4)));
            }
            #pragma unroll
            for(int c=0;c<6;c++){
                #pragma unroll
                for(int mi=0;mi<2;mi++){
                    #pragma unroll
                    for(int nj=0;nj<2;nj++){
                        mma16(Cr[mi][2*nj],   aF[PA[c]][mi], &bF[PB[c]][nj][0]);
                        mma16(Cr[mi][2*nj+1], aF[PA[c]][mi], &bF[PB[c]][nj][2]);
                    }
                }
            }
        }
    }
}

// qkv: C -> bf16 hi/lo planes of Q(scaled)/K/V
__global__ __launch_bounds__(128) void qkv_bf_kernel()
{
    extern __shared__ char sm[];
    int h = blockIdx.z, p = blockIdx.y, m0 = blockIdx.x*64;
    float Cr[2][4][4];
    #pragma unroll
    for(int mi=0;mi<2;mi++) for(int ni=0;ni<4;ni++) for(int e=0;e<4;e++) Cr[mi][ni][e]=0.f;
    const size_t xo = ((size_t)h*SEQ+m0)*FIN, wo = (size_t)h*HD*FIN;
    gemm_bf_main(g_X0+xo,g_X1+xo,g_X2+xo,FIN, g_W0[p]+wo,g_W1[p]+wo,g_W2[p]+wo,FIN, FIN, Cr, sm);

    bf *H = (p==0)?g_Qh:(p==1)?g_Kh:g_Vh;
    bf *L = (p==0)?g_Ql:(p==1)?g_Kl:g_Vl;
    const float sc = (p==0)? S_SCALE : 1.0f;
    const int tid = threadIdx.x, warp = tid>>5, lane = tid&31;
    const int g = lane>>2, q = lane&3;
    const int wm = (warp>>1)*32, wn = (warp&1)*32;
    #pragma unroll
    for(int mi=0;mi<2;mi++) for(int ni=0;ni<4;ni++){
        int row = wm+mi*16+g, col = wn+ni*8+2*q;
        uint32_t p0,p1;
        split2p(Cr[mi][ni][0]*sc, Cr[mi][ni][1]*sc, p0, p1);
        size_t o = ((size_t)h*SEQ + m0 + row)*HD + col;
        *(uint32_t*)(H+o)=p0; *(uint32_t*)(L+o)=p1;
        split2p(Cr[mi][ni][2]*sc, Cr[mi][ni][3]*sc, p0, p1);
        o += (size_t)8*HD;
        *(uint32_t*)(H+o)=p0; *(uint32_t*)(L+o)=p1;
    }
}

__global__ __launch_bounds__(128) void out_bf_kernel(float* __restrict__ Out)
{
    extern __shared__ char sm[];
    int m0 = blockIdx.x*64, n0 = blockIdx.y*64;
    float Cr[2][4][4];
    #pragma unroll
    for(int mi=0;mi<2;mi++) for(int ni=0;ni<4;ni++) for(int e=0;e<4;e++) Cr[mi][ni][e]=0.f;
    const size_t ho = (size_t)m0*FOUT, wo = (size_t)n0*(HNUM*HD);
    gemm_bf_main(g_H0+ho,g_H1+ho,g_H2+ho,FOUT, g_W0[3]+wo,g_W1[3]+wo,g_W2[3]+wo,HNUM*HD, FOUT, Cr, sm);

    const int tid = threadIdx.x, warp = tid>>5, lane = tid&31;
    const int g = lane>>2, q = lane&3;
    const int wm = (warp>>1)*32, wn = (warp&1)*32;
    #pragma unroll
    for(int mi=0;mi<2;mi++) for(int ni=0;ni<4;ni++){
        int row = m0+wm+mi*16+g, col = n0+wn+ni*8+2*q;
        *(float2*)(Out + (size_t)row*FOUT + col)     = make_float2(Cr[mi][ni][0],Cr[mi][ni][1]);
        *(float2*)(Out + (size_t)(row+8)*FOUT + col) = make_float2(Cr[mi][ni][2],Cr[mi][ni][3]);
    }
}

// ===================== bf16 flash: BM=256, BN=64, 16 warps =====================
#define NT (SEQ/64)
#define OFF_QH 0
#define OFF_QL 32768
#define OFF_K  65536
#define OFF_V  98304
#define OFF_M  131072
#define SMEM_FLASH 200704

__global__ __launch_bounds__(512,1) void flash_bf16_kernel(const int* __restrict__ mask)
{
    extern __shared__ char sm[];
    const uint32_t smb = smem_u32(sm);
    const int tid = threadIdx.x, warp = tid>>5, lane = tid&31;
    const int g = lane>>2, q = lane&3, r0 = warp*16;
    const int h = blockIdx.y, q0 = blockIdx.x*256;

    const bf* Qhg = g_Qh + ((size_t)h*SEQ+q0)*HD;
    const bf* Qlg = g_Ql + ((size_t)h*SEQ+q0)*HD;
    const bf* Khg = g_Kh + (size_t)h*SEQ*HD;
    const bf* Klg = g_Kl + (size_t)h*SEQ*HD;
    const bf* Vhg = g_Vh + (size_t)h*SEQ*HD;
    const bf* Vlg = g_Vl + (size_t)h*SEQ*HD;
    const int* mg = mask + ((size_t)h*SEQ+q0)*SEQ;
    int* Mi = (int*)(sm + OFF_M);

    const int a_row = (lane&7) + (lane&8);
    const int a_c16 = (lane>>4)&1;
    const int b_row = (lane&7) + ((lane&16)>>1);
    const int b_c16 = (lane>>3)&1;
    const uint32_t a_swz = (uint32_t)(lane&7)<<4;

    #pragma unroll
    for(int i=0;i<8;i++){
        int idx = tid+512*i, half = idx>>11, t = idx&2047, r = t>>3, s = t&7;
        const bf* src = (half? Qlg:Qhg) + (size_t)r*HD + s*8;
        cpa16s(smb + (half?OFF_QL:OFF_QH) + r*128 + ((s*16)^((r&7)<<4)), src);
    }
    auto stageKV = [&](int kt){
        const int k0 = kt*64, buf = kt&1;
        #pragma unroll
        for(int i=0;i<4;i++){
            int idx = tid+512*i, tens = idx>>9, t = idx&511, r = t>>3, s = t&7;
            const bf* sp = (tens==0)?Khg:(tens==1)?Klg:(tens==2)?Vhg:Vlg;
            uint32_t db = (tens<2 ? OFF_K : OFF_V) + buf*16384 + (tens&1)*8192;
            cpa16s(smb + db + r*128 + ((s*16)^((r&7)<<4)), sp + (size_t)(k0+r)*HD + s*8);
        }
    };
    auto stageM = [&](int kt){
        const int k0 = kt*64;
        #pragma unroll
        for(int i=0;i<8;i++){
            int idx = tid+512*i, r = idx>>4, s = idx&15;
            cpa16s(smb + OFF_M + (r*68 + s*4)*4, mg + (size_t)r*SEQ + k0 + s*4);
        }
    };
    stageKV(0); stageM(0); CP_COMMIT();

    float mr[2]={-1e30f,-1e30f}, lr[2]={0.f,0.f};
    float O[8][4];
    #pragma unroll
    for(int nt=0;nt<8;nt++) for(int e=0;e<4;e++) O[nt][e]=0.f;

    for(int kt=0;kt<NT;kt++){
        const int buf = kt&1;
        CP_WAIT0();
        __syncthreads();
        if(kt+1<NT){ stageKV(kt+1); CP_COMMIT(); }

        float S[8][4];
        #pragma unroll
        for(int nt=0;nt<8;nt++) for(int e=0;e<4;e++) S[nt][e]=0.f;
        #pragma unroll
        for(int kk4=0;kk4<4;kk4++){
            const uint32_t kkb = kk4*32;
            uint32_t ah[4], al[4];
            uint32_t qa = smb + OFF_QH + (r0+a_row)*128 + ((kkb + a_c16*16) ^ a_swz);
            ldsm4(ah, qa);
            ldsm4(al, qa + (OFF_QL-OFF_QH));
            #pragma unroll
            for(int ntp=0;ntp<4;ntp++){
                const int n0 = ntp*16;
                uint32_t bh[4], bl[4];
                uint32_t ka = smb + OFF_K + buf*16384 + (n0+b_row)*128 + ((kkb + b_c16*16) ^ ((uint32_t)(b_row&7)<<4));
                ldsm4(bh, ka);
                ldsm4(bl, ka + 8192);
                mma16(S[2*ntp],   ah, &bh[0]); mma16(S[2*ntp],   ah, &bl[0]); mma16(S[2*ntp],   al, &bh[0]);
                mma16(S[2*ntp+1], ah, &bh[2]); mma16(S[2*ntp+1], ah, &bl[2]); mma16(S[2*ntp+1], al, &bh[2]);
            }
        }

        const int rA = r0+g, rB = r0+8+g;
        float tmax[2]={-1e30f,-1e30f};
        #pragma unroll
        for(int nt=0;nt<8;nt++){
            int col = nt*8+2*q;
            int2 mA = *(const int2*)(Mi + rA*68 + col);
            int2 mB = *(const int2*)(Mi + rB*68 + col);
            if(!mA.x) S[nt][0]=-1e30f;
            if(!mA.y) S[nt][1]=-1e30f;
            if(!mB.x) S[nt][2]=-1e30f;
            if(!mB.y) S[nt][3]=-1e30f;
            tmax[0]=fmaxf(tmax[0],fmaxf(S[nt][0],S[nt][1]));
            tmax[1]=fmaxf(tmax[1],fmaxf(S[nt][2],S[nt][3]));
        }
        #pragma unroll
        for(int off=1;off<4;off<<=1){
            tmax[0]=fmaxf(tmax[0],__shfl_xor_sync(0xffffffffu,tmax[0],off));
            tmax[1]=fmaxf(tmax[1],__shfl_xor_sync(0xffffffffu,tmax[1],off));
        }
        float corr[2];
        #pragma unroll
        for(int hh=0;hh<2;hh++){
            float mnew = fmaxf(mr[hh], tmax[hh]);
            asm("ex2.approx.ftz.f32 %0,%1;" : "=f"(corr[hh]) : "f"(mr[hh]-mnew));
            mr[hh]=mnew; lr[hh]*=corr[hh];
            #pragma unroll
            for(int nt=0;nt<8;nt++){ O[nt][2*hh]*=corr[hh]; O[nt][2*hh+1]*=corr[hh]; }
        }
        float ts[2]={0.f,0.f};
        #pragma unroll
        for(int nt=0;nt<8;nt++){
            #pragma unroll
            for(int e=0;e<4;e++){
                float v; asm("ex2.approx.ftz.f32 %0,%1;" : "=f"(v) : "f"(S[nt][e]-mr[e>>1]));
                S[nt][e]=v; ts[e>>1]+=v;
            }
        }
        #pragma unroll
        for(int off=1;off<4;off<<=1){
            ts[0]+=__shfl_xor_sync(0xffffffffu,ts[0],off);
            ts[1]+=__shfl_xor_sync(0xffffffffu,ts[1],off);
        }
        lr[0]+=ts[0]; lr[1]+=ts[1];

        __syncthreads();
        if(kt+1<NT){ stageM(kt+1); CP_COMMIT(); }

        // ---- O += P V with P hi/lo split (3 products) ----
        #pragma unroll
        for(int ktp=0;ktp<4;ktp++){
            const float* s0 = S[2*ktp];
            const float* s1 = S[2*ktp+1];
            uint32_t a[4], alo[4];
            split2p(s0[0], s0[1], a[0], alo[0]);
            split2p(s0[2], s0[3], a[1], alo[1]);
            split2p(s1[0], s1[1], a[2], alo[2]);
            split2p(s1[2], s1[3], a[3], alo[3]);
            #pragma unroll
            for(int np=0;np<4;np++){
                const int n0 = np*16;
                uint32_t vh[4], vl[4];
                uint32_t va = smb + OFF_V + buf*16384 + (ktp*16 + a_row)*128 + ((n0*2 + a_c16*16) ^ a_swz);
                ldsm4t(vh, va);
                ldsm4t(vl, va + 8192);
                mma16(O[2*np],   a, &vh[0]); mma16(O[2*np],   a, &vl[0]); mma16(O[2*np],   alo, &vh[0]);
                mma16(O[2*np+1], a, &vh[2]); mma16(O[2*np+1], a, &vl[2]); mma16(O[2*np+1], alo, &vh[2]);
            }
        }
    }

    // ---- epilogue: 3-split Hcat planes ----
    #pragma unroll
    for(int hh=0;hh<2;hh++){
        float inv = 1.f/lr[hh];
        int row = q0 + r0 + hh*8 + g;
        size_t ob = (size_t)row*FOUT + h*HD;
        #pragma unroll
        for(int nt=0;nt<8;nt++){
            int col = nt*8+2*q;
            uint32_t p0,p1,p2;
            split3p(O[nt][2*hh]*inv, O[nt][2*hh+1]*inv, p0, p1, p2);
            *(uint32_t*)(g_H0+ob+col)=p0;
            *(uint32_t*)(g_H1+ob+col)=p1;
            *(uint32_t*)(g_H2+ob+col)=p2;
        }
    }
}

extern "C" void kernel_launch(void* const* d_in, const int* in_sizes, int n_in,
                              void* d_out, int out_size)
{
    const float* X  = (const float*)d_in[0];
    const int* mask = (const int*)d_in[1];
    const float* WQ = (const float*)d_in[2];
    const float* WK = (const float*)d_in[3];
    const float* WV = (const float*)d_in[4];
    const float* WO = (const float*)d_in[5];
    float* out = (float*)d_out;

    cudaFuncSetAttribute(flash_bf16_kernel, cudaFuncAttributeMaxDynamicSharedMemorySize, SMEM_FLASH);
    cudaFuncSetAttribute(qkv_bf_kernel, cudaFuncAttributeMaxDynamicSharedMemorySize, GP_SM);
    cudaFuncSetAttribute(out_bf_kernel, cudaFuncAttributeMaxDynamicSharedMemorySize, GP_SM);

    splitX_kernel<<<HNUM*SEQ*FIN/1024,256>>>(X);
    splitW_kernel<<<dim3(HNUM*HD*FIN/1024,4),256>>>(WQ,WK,WV,WO);
    qkv_bf_kernel<<<dim3(64,3,8),128,GP_SM>>>();
    flash_bf16_kernel<<<dim3(16,8),512,SMEM_FLASH>>>(mask);
    out_bf_kernel<<<dim3(64,8),128,GP_SM>>>(out);
}

// round 10
// speedup vs baseline: 2.0772x; 1.1017x over previous
#include <cuda_runtime.h>
#include <cuda_bf16.h>
#include <cuda_fp16.h>
#include <cstdint>

#define HNUM 8
#define SEQ  4096
#define FIN  512
#define HD   64
#define FOUT 512
#define S_SCALE 0.18033688011112042f  /* 0.125 * log2(e) */
typedef __nv_bfloat16 bf;

// split planes
__device__ bf g_X0[HNUM*SEQ*FIN], g_X1[HNUM*SEQ*FIN], g_X2[HNUM*SEQ*FIN];
__device__ bf g_W0[4][HNUM*HD*FIN], g_W1[4][HNUM*HD*FIN], g_W2[4][HNUM*HD*FIN];
__device__ bf g_Qh[HNUM*SEQ*HD], g_Ql[HNUM*SEQ*HD];
__device__ bf g_Kh[HNUM*SEQ*HD], g_Kl[HNUM*SEQ*HD];
__device__ __half g_Vh[HNUM*SEQ*HD], g_Vl[HNUM*SEQ*HD];
__device__ bf g_H0[SEQ*FOUT], g_H1[SEQ*FOUT], g_H2[SEQ*FOUT];

__device__ __forceinline__ uint32_t packbf(float hi, float lo){
    uint32_t d; asm("cvt.rn.bf16x2.f32 %0,%1,%2;" : "=r"(d) : "f"(hi), "f"(lo)); return d;
}
__device__ __forceinline__ uint32_t packh2(float hi, float lo){
    uint32_t d; asm("cvt.rn.f16x2.f32 %0,%1,%2;" : "=r"(d) : "f"(hi), "f"(lo)); return d;
}
__device__ __forceinline__ void split3p(float v0, float v1, uint32_t& p0, uint32_t& p1, uint32_t& p2){
    p0 = packbf(v1, v0);
    float a0 = v0 - __uint_as_float(p0<<16);
    float a1 = v1 - __uint_as_float(p0 & 0xFFFF0000u);
    p1 = packbf(a1, a0);
    float b0 = a0 - __uint_as_float(p1<<16);
    float b1 = a1 - __uint_as_float(p1 & 0xFFFF0000u);
    p2 = packbf(b1, b0);
}
__device__ __forceinline__ void split2p(float v0, float v1, uint32_t& p0, uint32_t& p1){
    p0 = packbf(v1, v0);
    p1 = packbf(v1 - __uint_as_float(p0 & 0xFFFF0000u), v0 - __uint_as_float(p0<<16));
}
__device__ __forceinline__ void split2h(float v0, float v1, uint32_t& p0, uint32_t& p1){
    p0 = packh2(v1, v0);
    float l0 = __half2float(__ushort_as_half((unsigned short)(p0 & 0xFFFFu)));
    float l1 = __half2float(__ushort_as_half((unsigned short)(p0 >> 16)));
    p1 = packh2(v1 - l1, v0 - l0);
}
__device__ __forceinline__ void cpa16s(uint32_t sa, const void* g){
    asm volatile("cp.async.cg.shared.global [%0],[%1],16;\n" :: "r"(sa),"l"(g));
}
#define CP_COMMIT() asm volatile("cp.async.commit_group;\n")
#define CP_WAIT1()  asm volatile("cp.async.wait_group 1;\n" ::: "memory")
#define CP_WAIT0()  asm volatile("cp.async.wait_group 0;\n" ::: "memory")
__device__ __forceinline__ uint32_t smem_u32(const void* p){
    uint32_t a; asm("{ .reg .u64 t; cvta.to.shared.u64 t, %1; cvt.u32.u64 %0, t; }" : "=r"(a) : "l"(p));
    return a;
}
__device__ __forceinline__ void ldsm4(uint32_t r[4], uint32_t a){
    asm volatile("ldmatrix.sync.aligned.m8n8.x4.shared.b16 {%0,%1,%2,%3},[%4];"
        : "=r"(r[0]),"=r"(r[1]),"=r"(r[2]),"=r"(r[3]) : "r"(a));
}
__device__ __forceinline__ void ldsm4t(uint32_t r[4], uint32_t a){
    asm volatile("ldmatrix.sync.aligned.m8n8.x4.trans.shared.b16 {%0,%1,%2,%3},[%4];"
        : "=r"(r[0]),"=r"(r[1]),"=r"(r[2]),"=r"(r[3]) : "r"(a));
}
__device__ __forceinline__ void mma16(float c[4], const uint32_t a[4], const uint32_t b[2]){
    asm volatile("mma.sync.aligned.m16n8k16.row.col.f32.bf16.bf16.f32 "
        "{%0,%1,%2,%3},{%4,%5,%6,%7},{%8,%9},{%0,%1,%2,%3};\n"
        : "+f"(c[0]),"+f"(c[1]),"+f"(c[2]),"+f"(c[3])
        : "r"(a[0]),"r"(a[1]),"r"(a[2]),"r"(a[3]),"r"(b[0]),"r"(b[1]));
}
__device__ __forceinline__ void mma16h(float c[4], const uint32_t a[4], const uint32_t b[2]){
    asm volatile("mma.sync.aligned.m16n8k16.row.col.f32.f16.f16.f32 "
        "{%0,%1,%2,%3},{%4,%5,%6,%7},{%8,%9},{%0,%1,%2,%3};\n"
        : "+f"(c[0]),"+f"(c[1]),"+f"(c[2]),"+f"(c[3])
        : "r"(a[0]),"r"(a[1]),"r"(a[2]),"r"(a[3]),"r"(b[0]),"r"(b[1]));
}

// ===================== split kernels =====================
__global__ __launch_bounds__(256) void splitX_kernel(const float* __restrict__ X)
{
    size_t i = ((size_t)blockIdx.x*256 + threadIdx.x)*4;
    float4 v = *(const float4*)(X+i);
    uint32_t a0,a1,a2,b0,b1,b2;
    split3p(v.x,v.y,a0,a1,a2); split3p(v.z,v.w,b0,b1,b2);
    *(uint32_t*)(g_X0+i)=a0; *(uint32_t*)(g_X0+i+2)=b0;
    *(uint32_t*)(g_X1+i)=a1; *(uint32_t*)(g_X1+i+2)=b1;
    *(uint32_t*)(g_X2+i)=a2; *(uint32_t*)(g_X2+i+2)=b2;
}
__global__ __launch_bounds__(256) void splitW_kernel(const float* __restrict__ WQ,
    const float* __restrict__ WK, const float* __restrict__ WV, const float* __restrict__ WO)
{
    int m = blockIdx.y;
    const float* src = (m==0)?WQ:(m==1)?WK:(m==2)?WV:WO;
    size_t i = ((size_t)blockIdx.x*256 + threadIdx.x)*4;
    float4 v = *(const float4*)(src+i);
    uint32_t a0,a1,a2,b0,b1,b2;
    split3p(v.x,v.y,a0,a1,a2); split3p(v.z,v.w,b0,b1,b2);
    *(uint32_t*)(g_W0[m]+i)=a0; *(uint32_t*)(g_W0[m]+i+2)=b0;
    *(uint32_t*)(g_W1[m]+i)=a1; *(uint32_t*)(g_W1[m]+i+2)=b1;
    *(uint32_t*)(g_W2[m]+i)=a2; *(uint32_t*)(g_W2[m]+i+2)=b2;
}

// ===================== bf16 6-product GEMM core (double-buffered) =====================
#define GP_SM 98304
__device__ __forceinline__ void gemm_bf_main(
    const bf* A0,const bf* A1,const bf* A2,int lda,
    const bf* B0,const bf* B1,const bf* B2,int ldb,
    int K, float Cr[2][4][4], char* sm)
{
    const uint32_t smb = smem_u32(sm);
    const int tid = threadIdx.x, warp = tid>>5, lane = tid&31;
    const int wm = (warp>>1)*32, wn = (warp&1)*32;
    const int a_row = (lane&7) + (lane&8);
    const int a_c16 = (lane>>4)&1;
    const int b_row = (lane&7) + ((lane&16)>>1);
    const int b_c16 = (lane>>3)&1;
    const bf* Ap[3] = {A0,A1,A2};
    const bf* Bp[3] = {B0,B1,B2};
    const int PA[6] = {0,0,1,1,0,2};
    const int PB[6] = {0,1,0,1,2,0};

    auto stage = [&](int buf, int k0){
        #pragma unroll
        for(int i=0;i<12;i++){
            int idx = tid+128*i, p = idx>>9, t = idx&511, r = t>>3, s = t&7;
            uint32_t off = buf*49152 + p*8192 + r*128 + ((s*16)^((r&7)<<4));
            cpa16s(smb + off, Ap[p] + (size_t)r*lda + k0 + s*8);
            cpa16s(smb + 24576 + off, Bp[p] + (size_t)r*ldb + k0 + s*8);
        }
    };
    stage(0,0); CP_COMMIT();
    const int nc = K/64;
    for(int c=0;c<nc;c++){
        const int buf = c&1;
        if(c+1<nc){ stage(buf^1, (c+1)*64); CP_COMMIT(); CP_WAIT1(); }
        else CP_WAIT0();
        __syncthreads();
        const uint32_t bb = smb + buf*49152;
        #pragma unroll
        for(int k16=0;k16<4;k16++){
            uint32_t aF[3][2][4], bF[3][2][4];
            #pragma unroll
            for(int p=0;p<3;p++){
                #pragma unroll
                for(int mi=0;mi<2;mi++)
                    ldsm4(aF[p][mi], bb + p*8192 + (wm+mi*16+a_row)*128 + ((k16*32 + a_c16*16)^((a_row&7)<<4)));
                #pragma unroll
                for(int nj=0;nj<2;nj++)
                    ldsm4(bF[p][nj], bb + 24576 + p*8192 + (wn+nj*16+b_row)*128 + ((k16*32 + b_c16*16)^((b_row&7)<<4)));
            }
            #pragma unroll
            for(int cc=0;cc<6;cc++){
                #pragma unroll
                for(int mi=0;mi<2;mi++){
                    #pragma unroll
                    for(int nj=0;nj<2;nj++){
                        mma16(Cr[mi][2*nj],   aF[PA[cc]][mi], &bF[PB[cc]][nj][0]);
                        mma16(Cr[mi][2*nj+1], aF[PA[cc]][mi], &bF[PB[cc]][nj][2]);
                    }
                }
            }
        }
        __syncthreads();
    }
}

// qkv: C -> bf16 hi/lo for Q(scaled)/K, fp16 hi/lo for V
__global__ __launch_bounds__(128) void qkv_bf_kernel()
{
    extern __shared__ char sm[];
    int h = blockIdx.z, p = blockIdx.y, m0 = blockIdx.x*64;
    float Cr[2][4][4];
    #pragma unroll
    for(int mi=0;mi<2;mi++) for(int ni=0;ni<4;ni++) for(int e=0;e<4;e++) Cr[mi][ni][e]=0.f;
    const size_t xo = ((size_t)h*SEQ+m0)*FIN, wo = (size_t)h*HD*FIN;
    gemm_bf_main(g_X0+xo,g_X1+xo,g_X2+xo,FIN, g_W0[p]+wo,g_W1[p]+wo,g_W2[p]+wo,FIN, FIN, Cr, sm);

    const float sc = (p==0)? S_SCALE : 1.0f;
    const int tid = threadIdx.x, warp = tid>>5, lane = tid&31;
    const int g = lane>>2, q = lane&3;
    const int wm = (warp>>1)*32, wn = (warp&1)*32;
    #pragma unroll
    for(int mi=0;mi<2;mi++) for(int ni=0;ni<4;ni++){
        int row = wm+mi*16+g, col = wn+ni*8+2*q;
        size_t o = ((size_t)h*SEQ + m0 + row)*HD + col;
        uint32_t p0,p1;
        if(p==2){
            split2h(Cr[mi][ni][0], Cr[mi][ni][1], p0, p1);
            *(uint32_t*)(g_Vh+o)=p0; *(uint32_t*)(g_Vl+o)=p1;
            split2h(Cr[mi][ni][2], Cr[mi][ni][3], p0, p1);
            *(uint32_t*)(g_Vh+o+8*HD)=p0; *(uint32_t*)(g_Vl+o+8*HD)=p1;
        }else{
            bf *H = (p==0)?g_Qh:g_Kh;
            bf *L = (p==0)?g_Ql:g_Kl;
            split2p(Cr[mi][ni][0]*sc, Cr[mi][ni][1]*sc, p0, p1);
            *(uint32_t*)(H+o)=p0; *(uint32_t*)(L+o)=p1;
            split2p(Cr[mi][ni][2]*sc, Cr[mi][ni][3]*sc, p0, p1);
            *(uint32_t*)(H+o+8*HD)=p0; *(uint32_t*)(L+o+8*HD)=p1;
        }
    }
}

__global__ __launch_bounds__(128) void out_bf_kernel(float* __restrict__ Out)
{
    extern __shared__ char sm[];
    int m0 = blockIdx.x*64, n0 = blockIdx.y*64;
    float Cr[2][4][4];
    #pragma unroll
    for(int mi=0;mi<2;mi++) for(int ni=0;ni<4;ni++) for(int e=0;e<4;e++) Cr[mi][ni][e]=0.f;
    const size_t ho = (size_t)m0*FOUT, wo = (size_t)n0*(HNUM*HD);
    gemm_bf_main(g_H0+ho,g_H1+ho,g_H2+ho,FOUT, g_W0[3]+wo,g_W1[3]+wo,g_W2[3]+wo,HNUM*HD, FOUT, Cr, sm);

    const int tid = threadIdx.x, warp = tid>>5, lane = tid&31;
    const int g = lane>>2, q = lane&3;
    const int wm = (warp>>1)*32, wn = (warp&1)*32;
    #pragma unroll
    for(int mi=0;mi<2;mi++) for(int ni=0;ni<4;ni++){
        int row = m0+wm+mi*16+g, col = n0+wn+ni*8+2*q;
        *(float2*)(Out + (size_t)row*FOUT + col)     = make_float2(Cr[mi][ni][0],Cr[mi][ni][1]);
        *(float2*)(Out + (size_t)(row+8)*FOUT + col) = make_float2(Cr[mi][ni][2],Cr[mi][ni][3]);
    }
}

// ===================== flash: BM=256, BN=64, 16 warps =====================
#define NT (SEQ/64)
#define OFF_QH 0
#define OFF_QL 32768
#define OFF_K  65536
#define OFF_V  98304
#define OFF_M  131072
#define SMEM_FLASH 200704

__global__ __launch_bounds__(512,1) void flash_bf16_kernel(const int* __restrict__ mask)
{
    extern __shared__ char sm[];
    const uint32_t smb = smem_u32(sm);
    const int tid = threadIdx.x, warp = tid>>5, lane = tid&31;
    const int g = lane>>2, q = lane&3, r0 = warp*16;
    const int h = blockIdx.y, q0 = blockIdx.x*256;

    const bf* Qhg = g_Qh + ((size_t)h*SEQ+q0)*HD;
    const bf* Qlg = g_Ql + ((size_t)h*SEQ+q0)*HD;
    const bf* Khg = g_Kh + (size_t)h*SEQ*HD;
    const bf* Klg = g_Kl + (size_t)h*SEQ*HD;
    const __half* Vhg = g_Vh + (size_t)h*SEQ*HD;
    const __half* Vlg = g_Vl + (size_t)h*SEQ*HD;
    const int* mg = mask + ((size_t)h*SEQ+q0)*SEQ;
    int* Mi = (int*)(sm + OFF_M);

    const int a_row = (lane&7) + (lane&8);
    const int a_c16 = (lane>>4)&1;
    const int b_row = (lane&7) + ((lane&16)>>1);
    const int b_c16 = (lane>>3)&1;
    const uint32_t a_swz = (uint32_t)(lane&7)<<4;

    #pragma unroll
    for(int i=0;i<8;i++){
        int idx = tid+512*i, half = idx>>11, t = idx&2047, r = t>>3, s = t&7;
        const bf* src = (half? Qlg:Qhg) + (size_t)r*HD + s*8;
        cpa16s(smb + (half?OFF_QL:OFF_QH) + r*128 + ((s*16)^((r&7)<<4)), src);
    }
    auto stageKV = [&](int kt){
        const int k0 = kt*64, buf = kt&1;
        #pragma unroll
        for(int i=0;i<4;i++){
            int idx = tid+512*i, tens = idx>>9, t = idx&511, r = t>>3, s = t&7;
            const void* sp = (tens==0)?(const void*)(Khg+(size_t)(k0+r)*HD+s*8)
                           :(tens==1)?(const void*)(Klg+(size_t)(k0+r)*HD+s*8)
                           :(tens==2)?(const void*)(Vhg+(size_t)(k0+r)*HD+s*8)
                                     :(const void*)(Vlg+(size_t)(k0+r)*HD+s*8);
            uint32_t db = (tens<2 ? OFF_K : OFF_V) + buf*16384 + (tens&1)*8192;
            cpa16s(smb + db + r*128 + ((s*16)^((r&7)<<4)), sp);
        }
    };
    auto stageM = [&](int kt){
        const int k0 = kt*64;
        #pragma unroll
        for(int i=0;i<8;i++){
            int idx = tid+512*i, r = idx>>4, s = idx&15;
            cpa16s(smb + OFF_M + (r*68 + s*4)*4, mg + (size_t)r*SEQ + k0 + s*4);
        }
    };
    stageKV(0); stageM(0); CP_COMMIT();

    float mr[2]={-1e30f,-1e30f}, lr[2]={0.f,0.f};
    float O[8][4];
    #pragma unroll
    for(int nt=0;nt<8;nt++) for(int e=0;e<4;e++) O[nt][e]=0.f;

    for(int kt=0;kt<NT;kt++){
        const int buf = kt&1;
        CP_WAIT0();
        __syncthreads();
        if(kt+1<NT){ stageKV(kt+1); CP_COMMIT(); }

        float S[8][4];
        #pragma unroll
        for(int nt=0;nt<8;nt++) for(int e=0;e<4;e++) S[nt][e]=0.f;
        #pragma unroll
        for(int kk4=0;kk4<4;kk4++){
            const uint32_t kkb = kk4*32;
            uint32_t ah[4], al[4];
            uint32_t qa = smb + OFF_QH + (r0+a_row)*128 + ((kkb + a_c16*16) ^ a_swz);
            ldsm4(ah, qa);
            ldsm4(al, qa + (OFF_QL-OFF_QH));
            #pragma unroll
            for(int ntp=0;ntp<4;ntp++){
                const int n0 = ntp*16;
                uint32_t bh[4], bl[4];
                uint32_t ka = smb + OFF_K + buf*16384 + (n0+b_row)*128 + ((kkb + b_c16*16) ^ ((uint32_t)(b_row&7)<<4));
                ldsm4(bh, ka);
                ldsm4(bl, ka + 8192);
                mma16(S[2*ntp],   ah, &bh[0]); mma16(S[2*ntp],   ah, &bl[0]); mma16(S[2*ntp],   al, &bh[0]);
                mma16(S[2*ntp+1], ah, &bh[2]); mma16(S[2*ntp+1], ah, &bl[2]); mma16(S[2*ntp+1], al, &bh[2]);
            }
        }

        const int rA = r0+g, rB = r0+8+g;
        float tmax[2]={-1e30f,-1e30f};
        #pragma unroll
        for(int nt=0;nt<8;nt++){
            int col = nt*8+2*q;
            int2 mA = *(const int2*)(Mi + rA*68 + col);
            int2 mB = *(const int2*)(Mi + rB*68 + col);
            if(!mA.x) S[nt][0]=-1e30f;
            if(!mA.y) S[nt][1]=-1e30f;
            if(!mB.x) S[nt][2]=-1e30f;
            if(!mB.y) S[nt][3]=-1e30f;
            tmax[0]=fmaxf(tmax[0],fmaxf(S[nt][0],S[nt][1]));
            tmax[1]=fmaxf(tmax[1],fmaxf(S[nt][2],S[nt][3]));
        }
        #pragma unroll
        for(int off=1;off<4;off<<=1){
            tmax[0]=fmaxf(tmax[0],__shfl_xor_sync(0xffffffffu,tmax[0],off));
            tmax[1]=fmaxf(tmax[1],__shfl_xor_sync(0xffffffffu,tmax[1],off));
        }
        float corr[2];
        #pragma unroll
        for(int hh=0;hh<2;hh++){
            float mnew = fmaxf(mr[hh], tmax[hh]);
            asm("ex2.approx.ftz.f32 %0,%1;" : "=f"(corr[hh]) : "f"(mr[hh]-mnew));
            mr[hh]=mnew; lr[hh]*=corr[hh];
            #pragma unroll
            for(int nt=0;nt<8;nt++){ O[nt][2*hh]*=corr[hh]; O[nt][2*hh+1]*=corr[hh]; }
        }
        float ts[2]={0.f,0.f};
        #pragma unroll
        for(int nt=0;nt<8;nt++){
            #pragma unroll
            for(int e=0;e<4;e++){
                float v; asm("ex2.approx.ftz.f32 %0,%1;" : "=f"(v) : "f"(S[nt][e]-mr[e>>1]));
                S[nt][e]=v; ts[e>>1]+=v;
            }
        }
        #pragma unroll
        for(int off=1;off<4;off<<=1){
            ts[0]+=__shfl_xor_sync(0xffffffffu,ts[0],off);
            ts[1]+=__shfl_xor_sync(0xffffffffu,ts[1],off);
        }
        lr[0]+=ts[0]; lr[1]+=ts[1];

        __syncthreads();
        if(kt+1<NT){ stageM(kt+1); CP_COMMIT(); }

        // ---- O += P V : fp16 P (single plane) x fp16 V (hi+lo) ----
        #pragma unroll
        for(int ktp=0;ktp<4;ktp++){
            const float* s0 = S[2*ktp];
            const float* s1 = S[2*ktp+1];
            uint32_t a[4] = { packh2(s0[1],s0[0]), packh2(s0[3],s0[2]),
                              packh2(s1[1],s1[0]), packh2(s1[3],s1[2]) };
            #pragma unroll
            for(int np=0;np<4;np++){
                const int n0 = np*16;
                uint32_t vh[4], vl[4];
                uint32_t va = smb + OFF_V + buf*16384 + (ktp*16 + a_row)*128 + ((n0*2 + a_c16*16) ^ a_swz);
                ldsm4t(vh, va);
                ldsm4t(vl, va + 8192);
                mma16h(O[2*np],   a, &vh[0]); mma16h(O[2*np],   a, &vl[0]);
                mma16h(O[2*np+1], a, &vh[2]); mma16h(O[2*np+1], a, &vl[2]);
            }
        }
    }

    // ---- epilogue: 3-split Hcat planes ----
    #pragma unroll
    for(int hh=0;hh<2;hh++){
        float inv = 1.f/lr[hh];
        int row = q0 + r0 + hh*8 + g;
        size_t ob = (size_t)row*FOUT + h*HD;
        #pragma unroll
        for(int nt=0;nt<8;nt++){
            int col = nt*8+2*q;
            uint32_t p0,p1,p2;
            split3p(O[nt][2*hh]*inv, O[nt][2*hh+1]*inv, p0, p1, p2);
            *(uint32_t*)(g_H0+ob+col)=p0;
            *(uint32_t*)(g_H1+ob+col)=p1;
            *(uint32_t*)(g_H2+ob+col)=p2;
        }
    }
}

extern "C" void kernel_launch(void* const* d_in, const int* in_sizes, int n_in,
                              void* d_out, int out_size)
{
    const float* X  = (const float*)d_in[0];
    const int* mask = (const int*)d_in[1];
    const float* WQ = (const float*)d_in[2];
    const float* WK = (const float*)d_in[3];
    const float* WV = (const float*)d_in[4];
    const float* WO = (const float*)d_in[5];
    float* out = (float*)d_out;

    cudaFuncSetAttribute(flash_bf16_kernel, cudaFuncAttributeMaxDynamicSharedMemorySize, SMEM_FLASH);
    cudaFuncSetAttribute(qkv_bf_kernel, cudaFuncAttributeMaxDynamicSharedMemorySize, GP_SM);
    cudaFuncSetAttribute(out_bf_kernel, cudaFuncAttributeMaxDynamicSharedMemorySize, GP_SM);

    splitX_kernel<<<HNUM*SEQ*FIN/1024,256>>>(X);
    splitW_kernel<<<dim3(HNUM*HD*FIN/1024,4),256>>>(WQ,WK,WV,WO);
    qkv_bf_kernel<<<dim3(64,3,8),128,GP_SM>>>();
    flash_bf16_kernel<<<dim3(16,8),512,SMEM_FLASH>>>(mask);
    out_bf_kernel<<<dim3(64,8),128,GP_SM>>>(out);
}

// round 11
// speedup vs baseline: 2.2972x; 1.1059x over previous
#include <cuda_runtime.h>
#include <cuda_bf16.h>
#include <cuda_fp16.h>
#include <cstdint>

#define HNUM 8
#define SEQ  4096
#define FIN  512
#define HD   64
#define FOUT 512
#define S_SCALE 0.18033688011112042f  /* 0.125 * log2(e) */
typedef __nv_bfloat16 bf;

__device__ bf g_X0[HNUM*SEQ*FIN], g_X1[HNUM*SEQ*FIN], g_X2[HNUM*SEQ*FIN];
__device__ bf g_W0[4][HNUM*HD*FIN], g_W1[4][HNUM*HD*FIN], g_W2[4][HNUM*HD*FIN];
__device__ bf g_Qh[HNUM*SEQ*HD], g_Ql[HNUM*SEQ*HD];
__device__ bf g_Kh[HNUM*SEQ*HD], g_Kl[HNUM*SEQ*HD];
__device__ __half g_Vh[HNUM*SEQ*HD];
__device__ bf g_H0[SEQ*FOUT], g_H1[SEQ*FOUT], g_H2[SEQ*FOUT];

__device__ __forceinline__ uint32_t packbf(float hi, float lo){
    uint32_t d; asm("cvt.rn.bf16x2.f32 %0,%1,%2;" : "=r"(d) : "f"(hi), "f"(lo)); return d;
}
__device__ __forceinline__ uint32_t packh2(float hi, float lo){
    uint32_t d; asm("cvt.rn.f16x2.f32 %0,%1,%2;" : "=r"(d) : "f"(hi), "f"(lo)); return d;
}
__device__ __forceinline__ void split3p(float v0, float v1, uint32_t& p0, uint32_t& p1, uint32_t& p2){
    p0 = packbf(v1, v0);
    float a0 = v0 - __uint_as_float(p0<<16);
    float a1 = v1 - __uint_as_float(p0 & 0xFFFF0000u);
    p1 = packbf(a1, a0);
    float b0 = a0 - __uint_as_float(p1<<16);
    float b1 = a1 - __uint_as_float(p1 & 0xFFFF0000u);
    p2 = packbf(b1, b0);
}
__device__ __forceinline__ void split2p(float v0, float v1, uint32_t& p0, uint32_t& p1){
    p0 = packbf(v1, v0);
    p1 = packbf(v1 - __uint_as_float(p0 & 0xFFFF0000u), v0 - __uint_as_float(p0<<16));
}
__device__ __forceinline__ void cpa16s(uint32_t sa, const void* g){
    asm volatile("cp.async.cg.shared.global [%0],[%1],16;\n" :: "r"(sa),"l"(g));
}
#define CP_COMMIT() asm volatile("cp.async.commit_group;\n")
#define CP_WAIT1()  asm volatile("cp.async.wait_group 1;\n" ::: "memory")
#define CP_WAIT0()  asm volatile("cp.async.wait_group 0;\n" ::: "memory")
__device__ __forceinline__ uint32_t smem_u32(const void* p){
    uint32_t a; asm("{ .reg .u64 t; cvta.to.shared.u64 t, %1; cvt.u32.u64 %0, t; }" : "=r"(a) : "l"(p));
    return a;
}
__device__ __forceinline__ void ldsm4(uint32_t r[4], uint32_t a){
    asm volatile("ldmatrix.sync.aligned.m8n8.x4.shared.b16 {%0,%1,%2,%3},[%4];"
        : "=r"(r[0]),"=r"(r[1]),"=r"(r[2]),"=r"(r[3]) : "r"(a));
}
__device__ __forceinline__ void ldsm4t(uint32_t r[4], uint32_t a){
    asm volatile("ldmatrix.sync.aligned.m8n8.x4.trans.shared.b16 {%0,%1,%2,%3},[%4];"
        : "=r"(r[0]),"=r"(r[1]),"=r"(r[2]),"=r"(r[3]) : "r"(a));
}
__device__ __forceinline__ void mma16(float c[4], const uint32_t a[4], const uint32_t b[2]){
    asm volatile("mma.sync.aligned.m16n8k16.row.col.f32.bf16.bf16.f32 "
        "{%0,%1,%2,%3},{%4,%5,%6,%7},{%8,%9},{%0,%1,%2,%3};\n"
        : "+f"(c[0]),"+f"(c[1]),"+f"(c[2]),"+f"(c[3])
        : "r"(a[0]),"r"(a[1]),"r"(a[2]),"r"(a[3]),"r"(b[0]),"r"(b[1]));
}
__device__ __forceinline__ void mma16h(float c[4], const uint32_t a[4], const uint32_t b[2]){
    asm volatile("mma.sync.aligned.m16n8k16.row.col.f32.f16.f16.f32 "
        "{%0,%1,%2,%3},{%4,%5,%6,%7},{%8,%9},{%0,%1,%2,%3};\n"
        : "+f"(c[0]),"+f"(c[1]),"+f"(c[2]),"+f"(c[3])
        : "r"(a[0]),"r"(a[1]),"r"(a[2]),"r"(a[3]),"r"(b[0]),"r"(b[1]));
}

// ===================== split kernels =====================
__global__ __launch_bounds__(256) void splitX_kernel(const float* __restrict__ X)
{
    size_t i = ((size_t)blockIdx.x*256 + threadIdx.x)*4;
    float4 v = *(const float4*)(X+i);
    uint32_t a0,a1,a2,b0,b1,b2;
    split3p(v.x,v.y,a0,a1,a2); split3p(v.z,v.w,b0,b1,b2);
    *(uint32_t*)(g_X0+i)=a0; *(uint32_t*)(g_X0+i+2)=b0;
    *(uint32_t*)(g_X1+i)=a1; *(uint32_t*)(g_X1+i+2)=b1;
    *(uint32_t*)(g_X2+i)=a2; *(uint32_t*)(g_X2+i+2)=b2;
}
__global__ __launch_bounds__(256) void splitW_kernel(const float* __restrict__ WQ,
    const float* __restrict__ WK, const float* __restrict__ WV, const float* __restrict__ WO)
{
    int m = blockIdx.y;
    const float* src = (m==0)?WQ:(m==1)?WK:(m==2)?WV:WO;
    size_t i = ((size_t)blockIdx.x*256 + threadIdx.x)*4;
    float4 v = *(const float4*)(src+i);
    uint32_t a0,a1,a2,b0,b1,b2;
    split3p(v.x,v.y,a0,a1,a2); split3p(v.z,v.w,b0,b1,b2);
    *(uint32_t*)(g_W0[m]+i)=a0; *(uint32_t*)(g_W0[m]+i+2)=b0;
    *(uint32_t*)(g_W1[m]+i)=a1; *(uint32_t*)(g_W1[m]+i+2)=b1;
    *(uint32_t*)(g_W2[m]+i)=a2; *(uint32_t*)(g_W2[m]+i+2)=b2;
}

// ===================== bf16 6-product GEMM core (double-buffered) =====================
#define GP_SM 98304
__device__ __forceinline__ void gemm_bf_main(
    const bf* A0,const bf* A1,const bf* A2,int lda,
    const bf* B0,const bf* B1,const bf* B2,int ldb,
    int K, float Cr[2][4][4], char* sm)
{
    const uint32_t smb = smem_u32(sm);
    const int tid = threadIdx.x, warp = tid>>5, lane = tid&31;
    const int wm = (warp>>1)*32, wn = (warp&1)*32;
    const int a_row = (lane&7) + (lane&8);
    const int a_c16 = (lane>>4)&1;
    const int b_row = (lane&7) + ((lane&16)>>1);
    const int b_c16 = (lane>>3)&1;
    const bf* Ap[3] = {A0,A1,A2};
    const bf* Bp[3] = {B0,B1,B2};
    const int PA[6] = {0,0,1,1,0,2};
    const int PB[6] = {0,1,0,1,2,0};

    auto stage = [&](int buf, int k0){
        #pragma unroll
        for(int i=0;i<12;i++){
            int idx = tid+128*i, p = idx>>9, t = idx&511, r = t>>3, s = t&7;
            uint32_t off = buf*49152 + p*8192 + r*128 + ((s*16)^((r&7)<<4));
            cpa16s(smb + off, Ap[p] + (size_t)r*lda + k0 + s*8);
            cpa16s(smb + 24576 + off, Bp[p] + (size_t)r*ldb + k0 + s*8);
        }
    };
    stage(0,0); CP_COMMIT();
    const int nc = K/64;
    for(int c=0;c<nc;c++){
        const int buf = c&1;
        if(c+1<nc){ stage(buf^1, (c+1)*64); CP_COMMIT(); CP_WAIT1(); }
        else CP_WAIT0();
        __syncthreads();
        const uint32_t bb = smb + buf*49152;
        #pragma unroll
        for(int k16=0;k16<4;k16++){
            uint32_t aF[3][2][4], bF[3][2][4];
            #pragma unroll
            for(int p=0;p<3;p++){
                #pragma unroll
                for(int mi=0;mi<2;mi++)
                    ldsm4(aF[p][mi], bb + p*8192 + (wm+mi*16+a_row)*128 + ((k16*32 + a_c16*16)^((a_row&7)<<4)));
                #pragma unroll
                for(int nj=0;nj<2;nj++)
                    ldsm4(bF[p][nj], bb + 24576 + p*8192 + (wn+nj*16+b_row)*128 + ((k16*32 + b_c16*16)^((b_row&7)<<4)));
            }
            #pragma unroll
            for(int cc=0;cc<6;cc++){
                #pragma unroll
                for(int mi=0;mi<2;mi++){
                    #pragma unroll
                    for(int nj=0;nj<2;nj++){
                        mma16(Cr[mi][2*nj],   aF[PA[cc]][mi], &bF[PB[cc]][nj][0]);
                        mma16(Cr[mi][2*nj+1], aF[PA[cc]][mi], &bF[PB[cc]][nj][2]);
                    }
                }
            }
        }
        __syncthreads();
    }
}

// qkv: C -> bf16 hi/lo for Q(scaled)/K, fp16 (single plane) for V
__global__ __launch_bounds__(128) void qkv_bf_kernel()
{
    extern __shared__ char sm[];
    int h = blockIdx.z, p = blockIdx.y, m0 = blockIdx.x*64;
    float Cr[2][4][4];
    #pragma unroll
    for(int mi=0;mi<2;mi++) for(int ni=0;ni<4;ni++) for(int e=0;e<4;e++) Cr[mi][ni][e]=0.f;
    const size_t xo = ((size_t)h*SEQ+m0)*FIN, wo = (size_t)h*HD*FIN;
    gemm_bf_main(g_X0+xo,g_X1+xo,g_X2+xo,FIN, g_W0[p]+wo,g_W1[p]+wo,g_W2[p]+wo,FIN, FIN, Cr, sm);

    const float sc = (p==0)? S_SCALE : 1.0f;
    const int tid = threadIdx.x, warp = tid>>5, lane = tid&31;
    const int g = lane>>2, q = lane&3;
    const int wm = (warp>>1)*32, wn = (warp&1)*32;
    #pragma unroll
    for(int mi=0;mi<2;mi++) for(int ni=0;ni<4;ni++){
        int row = wm+mi*16+g, col = wn+ni*8+2*q;
        size_t o = ((size_t)h*SEQ + m0 + row)*HD + col;
        uint32_t p0,p1;
        if(p==2){
            *(uint32_t*)(g_Vh+o)        = packh2(Cr[mi][ni][1], Cr[mi][ni][0]);
            *(uint32_t*)(g_Vh+o+8*HD)   = packh2(Cr[mi][ni][3], Cr[mi][ni][2]);
        }else{
            bf *H = (p==0)?g_Qh:g_Kh;
            bf *L = (p==0)?g_Ql:g_Kl;
            split2p(Cr[mi][ni][0]*sc, Cr[mi][ni][1]*sc, p0, p1);
            *(uint32_t*)(H+o)=p0; *(uint32_t*)(L+o)=p1;
            split2p(Cr[mi][ni][2]*sc, Cr[mi][ni][3]*sc, p0, p1);
            *(uint32_t*)(H+o+8*HD)=p0; *(uint32_t*)(L+o+8*HD)=p1;
        }
    }
}

__global__ __launch_bounds__(128) void out_bf_kernel(float* __restrict__ Out)
{
    extern __shared__ char sm[];
    int m0 = blockIdx.x*64, n0 = blockIdx.y*64;
    float Cr[2][4][4];
    #pragma unroll
    for(int mi=0;mi<2;mi++) for(int ni=0;ni<4;ni++) for(int e=0;e<4;e++) Cr[mi][ni][e]=0.f;
    const size_t ho = (size_t)m0*FOUT, wo = (size_t)n0*(HNUM*HD);
    gemm_bf_main(g_H0+ho,g_H1+ho,g_H2+ho,FOUT, g_W0[3]+wo,g_W1[3]+wo,g_W2[3]+wo,HNUM*HD, FOUT, Cr, sm);

    const int tid = threadIdx.x, warp = tid>>5, lane = tid&31;
    const int g = lane>>2, q = lane&3;
    const int wm = (warp>>1)*32, wn = (warp&1)*32;
    #pragma unroll
    for(int mi=0;mi<2;mi++) for(int ni=0;ni<4;ni++){
        int row = m0+wm+mi*16+g, col = n0+wn+ni*8+2*q;
        *(float2*)(Out + (size_t)row*FOUT + col)     = make_float2(Cr[mi][ni][0],Cr[mi][ni][1]);
        *(float2*)(Out + (size_t)(row+8)*FOUT + col) = make_float2(Cr[mi][ni][2],Cr[mi][ni][3]);
    }
}

// ===================== flash: BM=256, BN=64, 16 warps, QK(t+1)-before-PV(t) =====================
#define NT (SEQ/64)
#define OFF_QH 0
#define OFF_QL 32768
#define OFF_K  65536      /* 3 bufs x (Kh 8K | Kl 8K) */
#define OFF_V  114688     /* 3 bufs x 8K (fp16, single plane) */
#define OFF_M  139264     /* int [256][68] single buffer */
#define SMEM_FLASH 208896

__global__ __launch_bounds__(512,1) void flash_bf16_kernel(const int* __restrict__ mask)
{
    extern __shared__ char sm[];
    const uint32_t smb = smem_u32(sm);
    const int tid = threadIdx.x, warp = tid>>5, lane = tid&31;
    const int g = lane>>2, q = lane&3, r0 = warp*16;
    const int h = blockIdx.y, q0 = blockIdx.x*256;

    const bf* Qhg = g_Qh + ((size_t)h*SEQ+q0)*HD;
    const bf* Qlg = g_Ql + ((size_t)h*SEQ+q0)*HD;
    const bf* Khg = g_Kh + (size_t)h*SEQ*HD;
    const bf* Klg = g_Kl + (size_t)h*SEQ*HD;
    const __half* Vhg = g_Vh + (size_t)h*SEQ*HD;
    const int* mg = mask + ((size_t)h*SEQ+q0)*SEQ;
    int* Mi = (int*)(sm + OFF_M);

    const int a_row = (lane&7) + (lane&8);
    const int a_c16 = (lane>>4)&1;
    const int b_row = (lane&7) + ((lane&16)>>1);
    const int b_c16 = (lane>>3)&1;
    const uint32_t a_swz = (uint32_t)(lane&7)<<4;

    // stage Q (bf16 hi/lo, swizzled)
    #pragma unroll
    for(int i=0;i<8;i++){
        int idx = tid+512*i, half = idx>>11, t = idx&2047, r = t>>3, s = t&7;
        const bf* src = (half? Qlg:Qhg) + (size_t)r*HD + s*8;
        cpa16s(smb + (half?OFF_QL:OFF_QH) + r*128 + ((s*16)^((r&7)<<4)), src);
    }
    auto stageKV = [&](int kt){
        const int k0 = kt*64, buf = kt%3;
        #pragma unroll
        for(int i=0;i<3;i++){
            int idx = tid+512*i, tens = idx>>9, t = idx&511, r = t>>3, s = t&7;
            uint32_t sw = r*128 + ((s*16)^((r&7)<<4));
            if(tens<2) cpa16s(smb + OFF_K + buf*16384 + tens*8192 + sw,
                              (tens? Klg:Khg) + (size_t)(k0+r)*HD + s*8);
            else       cpa16s(smb + OFF_V + buf*8192 + sw, Vhg + (size_t)(k0+r)*HD + s*8);
        }
    };
    auto stageM = [&](int kt){
        const int k0 = kt*64;
        #pragma unroll
        for(int i=0;i<8;i++){
            int idx = tid+512*i, r = idx>>4, s = idx&15;
            cpa16s(smb + OFF_M + (r*68 + s*4)*4, mg + (size_t)r*SEQ + k0 + s*4);
        }
    };

    float S[8][4], O[8][4];
    #pragma unroll
    for(int nt=0;nt<8;nt++) for(int e=0;e<4;e++){ S[nt][e]=0.f; O[nt][e]=0.f; }
    float mr[2]={-1e30f,-1e30f}, lr[2]={0.f,0.f};
    uint32_t P[8][2];

    auto QK = [&](int kt){
        const int buf = kt%3;
        #pragma unroll
        for(int kk4=0;kk4<4;kk4++){
            const uint32_t kkb = kk4*32;
            uint32_t ah[4], al[4];
            uint32_t qa = smb + OFF_QH + (r0+a_row)*128 + ((kkb + a_c16*16) ^ a_swz);
            ldsm4(ah, qa);
            ldsm4(al, qa + 32768);
            #pragma unroll
            for(int ntp=0;ntp<4;ntp++){
                uint32_t bh[4], bl[4];
                uint32_t ka = smb + OFF_K + buf*16384 + (ntp*16+b_row)*128 + ((kkb + b_c16*16) ^ ((uint32_t)(b_row&7)<<4));
                ldsm4(bh, ka);
                ldsm4(bl, ka + 8192);
                mma16(S[2*ntp],   ah, &bh[0]); mma16(S[2*ntp],   ah, &bl[0]); mma16(S[2*ntp],   al, &bh[0]);
                mma16(S[2*ntp+1], ah, &bh[2]); mma16(S[2*ntp+1], ah, &bl[2]); mma16(S[2*ntp+1], al, &bh[2]);
            }
        }
    };
    auto PV = [&](int kt){
        const int buf = kt%3;
        #pragma unroll
        for(int ktp=0;ktp<4;ktp++){
            uint32_t a[4] = { P[2*ktp][0], P[2*ktp][1], P[2*ktp+1][0], P[2*ktp+1][1] };
            #pragma unroll
            for(int np=0;np<4;np++){
                uint32_t vh[4];
                uint32_t va = smb + OFF_V + buf*8192 + (ktp*16 + a_row)*128 + ((np*32 + a_c16*16) ^ a_swz);
                ldsm4t(vh, va);
                mma16h(O[2*np],   a, &vh[0]);
                mma16h(O[2*np+1], a, &vh[2]);
            }
        }
    };

    // prologue: group0 = Q + M(0) + KV(0); group1 = KV(1)
    stageM(0); stageKV(0); CP_COMMIT();
    stageKV(1); CP_COMMIT();
    CP_WAIT1();
    __syncthreads();
    QK(0);

    for(int t=0;t<NT;t++){
        if(t==NT-1) CP_WAIT0(); else CP_WAIT1();   // M(t) arrived

        // ---- softmax(t) ----
        const int rA = r0+g, rB = r0+8+g;
        float tmax[2]={-1e30f,-1e30f};
        #pragma unroll
        for(int nt=0;nt<8;nt++){
            int col = nt*8+2*q;
            int2 mA = *(const int2*)(Mi + rA*68 + col);
            int2 mB = *(const int2*)(Mi + rB*68 + col);
            if(!mA.x) S[nt][0]=-1e30f;
            if(!mA.y) S[nt][1]=-1e30f;
            if(!mB.x) S[nt][2]=-1e30f;
            if(!mB.y) S[nt][3]=-1e30f;
            tmax[0]=fmaxf(tmax[0],fmaxf(S[nt][0],S[nt][1]));
            tmax[1]=fmaxf(tmax[1],fmaxf(S[nt][2],S[nt][3]));
        }
        #pragma unroll
        for(int off=1;off<4;off<<=1){
            tmax[0]=fmaxf(tmax[0],__shfl_xor_sync(0xffffffffu,tmax[0],off));
            tmax[1]=fmaxf(tmax[1],__shfl_xor_sync(0xffffffffu,tmax[1],off));
        }
        float corr[2];
        #pragma unroll
        for(int hh=0;hh<2;hh++){
            float mnew = fmaxf(mr[hh], tmax[hh]);
            asm("ex2.approx.ftz.f32 %0,%1;" : "=f"(corr[hh]) : "f"(mr[hh]-mnew));
            mr[hh]=mnew;
        }
        float ts[2]={0.f,0.f};
        #pragma unroll
        for(int nt=0;nt<8;nt++){
            #pragma unroll
            for(int e=0;e<4;e++){
                float v; asm("ex2.approx.ftz.f32 %0,%1;" : "=f"(v) : "f"(S[nt][e]-mr[e>>1]));
                S[nt][e]=v; ts[e>>1]+=v;
            }
        }
        #pragma unroll
        for(int off=1;off<4;off<<=1){
            ts[0]+=__shfl_xor_sync(0xffffffffu,ts[0],off);
            ts[1]+=__shfl_xor_sync(0xffffffffu,ts[1],off);
        }
        lr[0]=lr[0]*corr[0]+ts[0]; lr[1]=lr[1]*corr[1]+ts[1];
        // pack P (frees S), then rescale O (stalls only on PV(t-1) completion)
        #pragma unroll
        for(int nt=0;nt<8;nt++){
            P[nt][0] = packh2(S[nt][1], S[nt][0]);
            P[nt][1] = packh2(S[nt][3], S[nt][2]);
        }
        #pragma unroll
        for(int nt=0;nt<8;nt++){
            O[nt][0]*=corr[0]; O[nt][1]*=corr[0];
            O[nt][2]*=corr[1]; O[nt][3]*=corr[1];
        }

        __syncthreads();   // all warps consumed M(t) & done with (t-1) buffers

        if(t+1<NT){
            stageM(t+1); CP_COMMIT();
            CP_WAIT1();                      // KV(t+1) resident
            #pragma unroll
            for(int nt=0;nt<8;nt++) for(int e=0;e<4;e++) S[nt][e]=0.f;
            QK(t+1);                         // queued BEFORE PV(t)
        }
        if(t+2<NT){ stageKV(t+2); CP_COMMIT(); }
        PV(t);                               // drains under softmax(t+1)
    }

    // ---- epilogue: 3-split Hcat planes ----
    #pragma unroll
    for(int hh=0;hh<2;hh++){
        float inv = 1.f/lr[hh];
        int row = q0 + r0 + hh*8 + g;
        size_t ob = (size_t)row*FOUT + h*HD;
        #pragma unroll
        for(int nt=0;nt<8;nt++){
            int col = nt*8+2*q;
            uint32_t p0,p1,p2;
            split3p(O[nt][2*hh]*inv, O[nt][2*hh+1]*inv, p0, p1, p2);
            *(uint32_t*)(g_H0+ob+col)=p0;
            *(uint32_t*)(g_H1+ob+col)=p1;
            *(uint32_t*)(g_H2+ob+col)=p2;
        }
    }
}

extern "C" void kernel_launch(void* const* d_in, const int* in_sizes, int n_in,
                              void* d_out, int out_size)
{
    const float* X  = (const float*)d_in[0];
    const int* mask = (const int*)d_in[1];
    const float* WQ = (const float*)d_in[2];
    const float* WK = (const float*)d_in[3];
    const float* WV = (const float*)d_in[4];
    const float* WO = (const float*)d_in[5];
    float* out = (float*)d_out;

    cudaFuncSetAttribute(flash_bf16_kernel, cudaFuncAttributeMaxDynamicSharedMemorySize, SMEM_FLASH);
    cudaFuncSetAttribute(qkv_bf_kernel, cudaFuncAttributeMaxDynamicSharedMemorySize, GP_SM);
    cudaFuncSetAttribute(out_bf_kernel, cudaFuncAttributeMaxDynamicSharedMemorySize, GP_SM);

    splitX_kernel<<<HNUM*SEQ*FIN/1024,256>>>(X);
    splitW_kernel<<<dim3(HNUM*HD*FIN/1024,4),256>>>(WQ,WK,WV,WO);
    qkv_bf_kernel<<<dim3(64,3,8),128,GP_SM>>>();
    flash_bf16_kernel<<<dim3(16,8),512,SMEM_FLASH>>>(mask);
    out_bf_kernel<<<dim3(64,8),128,GP_SM>>>(out);
}

// round 13
// speedup vs baseline: 2.6605x; 1.1582x over previous
#include <cuda_runtime.h>
#include <cuda_bf16.h>
#include <cuda_fp16.h>
#include <cstdint>

#define HNUM 8
#define SEQ  4096
#define FIN  512
#define HD   64
#define FOUT 512
#define S_SCALE 0.18033688011112042f  /* 0.125 * log2(e) */
typedef __nv_bfloat16 bf;

__device__ bf g_X0[HNUM*SEQ*FIN], g_X1[HNUM*SEQ*FIN];
__device__ bf g_W0[4][HNUM*HD*FIN], g_W1[4][HNUM*HD*FIN];
__device__ bf g_Qh[HNUM*SEQ*HD], g_Ql[HNUM*SEQ*HD];
__device__ bf g_Kh[HNUM*SEQ*HD], g_Kl[HNUM*SEQ*HD];
__device__ __half g_Vh[HNUM*SEQ*HD];
__device__ bf g_H0[SEQ*FOUT], g_H1[SEQ*FOUT];

__device__ __forceinline__ uint32_t packbf(float hi, float lo){
    uint32_t d; asm("cvt.rn.bf16x2.f32 %0,%1,%2;" : "=r"(d) : "f"(hi), "f"(lo)); return d;
}
__device__ __forceinline__ uint32_t packh2(float hi, float lo){
    uint32_t d; asm("cvt.rn.f16x2.f32 %0,%1,%2;" : "=r"(d) : "f"(hi), "f"(lo)); return d;
}
__device__ __forceinline__ void split2p(float v0, float v1, uint32_t& p0, uint32_t& p1){
    p0 = packbf(v1, v0);
    p1 = packbf(v1 - __uint_as_float(p0 & 0xFFFF0000u), v0 - __uint_as_float(p0<<16));
}
__device__ __forceinline__ void cpa16s(uint32_t sa, const void* g){
    asm volatile("cp.async.cg.shared.global [%0],[%1],16;\n" :: "r"(sa),"l"(g));
}
#define CP_COMMIT() asm volatile("cp.async.commit_group;\n")
#define CP_WAIT1()  asm volatile("cp.async.wait_group 1;\n" ::: "memory")
#define CP_WAIT0()  asm volatile("cp.async.wait_group 0;\n" ::: "memory")
__device__ __forceinline__ uint32_t smem_u32(const void* p){
    uint32_t a; asm("{ .reg .u64 t; cvta.to.shared.u64 t, %1; cvt.u32.u64 %0, t; }" : "=r"(a) : "l"(p));
    return a;
}
__device__ __forceinline__ void ldsm4(uint32_t r[4], uint32_t a){
    asm volatile("ldmatrix.sync.aligned.m8n8.x4.shared.b16 {%0,%1,%2,%3},[%4];"
        : "=r"(r[0]),"=r"(r[1]),"=r"(r[2]),"=r"(r[3]) : "r"(a));
}
__device__ __forceinline__ void ldsm4t(uint32_t r[4], uint32_t a){
    asm volatile("ldmatrix.sync.aligned.m8n8.x4.trans.shared.b16 {%0,%1,%2,%3},[%4];"
        : "=r"(r[0]),"=r"(r[1]),"=r"(r[2]),"=r"(r[3]) : "r"(a));
}
__device__ __forceinline__ void mma16(float c[4], const uint32_t a[4], const uint32_t b[2]){
    asm volatile("mma.sync.aligned.m16n8k16.row.col.f32.bf16.bf16.f32 "
        "{%0,%1,%2,%3},{%4,%5,%6,%7},{%8,%9},{%0,%1,%2,%3};\n"
        : "+f"(c[0]),"+f"(c[1]),"+f"(c[2]),"+f"(c[3])
        : "r"(a[0]),"r"(a[1]),"r"(a[2]),"r"(a[3]),"r"(b[0]),"r"(b[1]));
}
__device__ __forceinline__ void mma16h(float c[4], const uint32_t a[4], const uint32_t b[2]){
    asm volatile("mma.sync.aligned.m16n8k16.row.col.f32.f16.f16.f32 "
        "{%0,%1,%2,%3},{%4,%5,%6,%7},{%8,%9},{%0,%1,%2,%3};\n"
        : "+f"(c[0]),"+f"(c[1]),"+f"(c[2]),"+f"(c[3])
        : "r"(a[0]),"r"(a[1]),"r"(a[2]),"r"(a[3]),"r"(b[0]),"r"(b[1]));
}

// ===================== split kernels (2 planes) =====================
__global__ __launch_bounds__(256) void splitX_kernel(const float* __restrict__ X)
{
    size_t i = ((size_t)blockIdx.x*256 + threadIdx.x)*4;
    float4 v = *(const float4*)(X+i);
    uint32_t a0,a1,b0,b1;
    split2p(v.x,v.y,a0,a1); split2p(v.z,v.w,b0,b1);
    *(uint32_t*)(g_X0+i)=a0; *(uint32_t*)(g_X0+i+2)=b0;
    *(uint32_t*)(g_X1+i)=a1; *(uint32_t*)(g_X1+i+2)=b1;
}
__global__ __launch_bounds__(256) void splitW_kernel(const float* __restrict__ WQ,
    const float* __restrict__ WK, const float* __restrict__ WV, const float* __restrict__ WO)
{
    int m = blockIdx.y;
    const float* src = (m==0)?WQ:(m==1)?WK:(m==2)?WV:WO;
    size_t i = ((size_t)blockIdx.x*256 + threadIdx.x)*4;
    float4 v = *(const float4*)(src+i);
    uint32_t a0,a1,b0,b1;
    split2p(v.x,v.y,a0,a1); split2p(v.z,v.w,b0,b1);
    *(uint32_t*)(g_W0[m]+i)=a0; *(uint32_t*)(g_W0[m]+i+2)=b0;
    *(uint32_t*)(g_W1[m]+i)=a1; *(uint32_t*)(g_W1[m]+i+2)=b1;
}

// ===================== bf16 2-plane 3-product GEMM core (double-buffered) =====================
#define GP_SM 65536
__device__ __forceinline__ void gemm_bf_main(
    const bf* A0,const bf* A1,int lda,
    const bf* B0,const bf* B1,int ldb,
    int K, float Cr[2][4][4], char* sm)
{
    const uint32_t smb = smem_u32(sm);
    const int tid = threadIdx.x, warp = tid>>5, lane = tid&31;
    const int wm = (warp>>1)*32, wn = (warp&1)*32;
    const int a_row = (lane&7) + (lane&8);
    const int a_c16 = (lane>>4)&1;
    const int b_row = (lane&7) + ((lane&16)>>1);
    const int b_c16 = (lane>>3)&1;
    const bf* Ap[2] = {A0,A1};
    const bf* Bp[2] = {B0,B1};
    const int PA[3] = {0,0,1};
    const int PB[3] = {0,1,0};

    auto stage = [&](int buf, int k0){
        #pragma unroll
        for(int i=0;i<16;i++){
            int idx = tid+128*i, side = idx>>10, p = (idx>>9)&1, t = idx&511, r = t>>3, s = t&7;
            uint32_t off = buf*32768 + side*16384 + p*8192 + r*128 + ((s*16)^((r&7)<<4));
            const bf* src = side? Bp[p] : Ap[p];
            int ld = side? ldb : lda;
            cpa16s(smb + off, src + (size_t)r*ld + k0 + s*8);
        }
    };
    stage(0,0); CP_COMMIT();
    const int nc = K/64;
    for(int c=0;c<nc;c++){
        const int buf = c&1;
        if(c+1<nc){ stage(buf^1, (c+1)*64); CP_COMMIT(); CP_WAIT1(); }
        else CP_WAIT0();
        __syncthreads();
        const uint32_t bb = smb + buf*32768;
        #pragma unroll
        for(int k16=0;k16<4;k16++){
            uint32_t aF[2][2][4], bF[2][2][4];
            #pragma unroll
            for(int p=0;p<2;p++){
                #pragma unroll
                for(int mi=0;mi<2;mi++)
                    ldsm4(aF[p][mi], bb + p*8192 + (wm+mi*16+a_row)*128 + ((k16*32 + a_c16*16)^((a_row&7)<<4)));
                #pragma unroll
                for(int nj=0;nj<2;nj++)
                    ldsm4(bF[p][nj], bb + 16384 + p*8192 + (wn+nj*16+b_row)*128 + ((k16*32 + b_c16*16)^((b_row&7)<<4)));
            }
            #pragma unroll
            for(int cc=0;cc<3;cc++){
                #pragma unroll
                for(int mi=0;mi<2;mi++){
                    #pragma unroll
                    for(int nj=0;nj<2;nj++){
                        mma16(Cr[mi][2*nj],   aF[PA[cc]][mi], &bF[PB[cc]][nj][0]);
                        mma16(Cr[mi][2*nj+1], aF[PA[cc]][mi], &bF[PB[cc]][nj][2]);
                    }
                }
            }
        }
        __syncthreads();
    }
}

// qkv: C -> bf16 hi/lo for Q(scaled)/K, fp16 single plane for V
__global__ __launch_bounds__(128) void qkv_bf_kernel()
{
    extern __shared__ char sm[];
    int h = blockIdx.z, p = blockIdx.y, m0 = blockIdx.x*64;
    float Cr[2][4][4];
    #pragma unroll
    for(int mi=0;mi<2;mi++) for(int ni=0;ni<4;ni++) for(int e=0;e<4;e++) Cr[mi][ni][e]=0.f;
    const size_t xo = ((size_t)h*SEQ+m0)*FIN, wo = (size_t)h*HD*FIN;
    gemm_bf_main(g_X0+xo,g_X1+xo,FIN, g_W0[p]+wo,g_W1[p]+wo,FIN, FIN, Cr, sm);

    const float sc = (p==0)? S_SCALE : 1.0f;
    const int tid = threadIdx.x, warp = tid>>5, lane = tid&31;
    const int g = lane>>2, q = lane&3;
    const int wm = (warp>>1)*32, wn = (warp&1)*32;
    #pragma unroll
    for(int mi=0;mi<2;mi++) for(int ni=0;ni<4;ni++){
        int row = wm+mi*16+g, col = wn+ni*8+2*q;
        size_t o = ((size_t)h*SEQ + m0 + row)*HD + col;
        uint32_t p0,p1;
        if(p==2){
            *(uint32_t*)(g_Vh+o)      = packh2(Cr[mi][ni][1], Cr[mi][ni][0]);
            *(uint32_t*)(g_Vh+o+8*HD) = packh2(Cr[mi][ni][3], Cr[mi][ni][2]);
        }else{
            bf *H = (p==0)?g_Qh:g_Kh;
            bf *L = (p==0)?g_Ql:g_Kl;
            split2p(Cr[mi][ni][0]*sc, Cr[mi][ni][1]*sc, p0, p1);
            *(uint32_t*)(H+o)=p0; *(uint32_t*)(L+o)=p1;
            split2p(Cr[mi][ni][2]*sc, Cr[mi][ni][3]*sc, p0, p1);
            *(uint32_t*)(H+o+8*HD)=p0; *(uint32_t*)(L+o+8*HD)=p1;
        }
    }
}

__global__ __launch_bounds__(128) void out_bf_kernel(float* __restrict__ Out)
{
    extern __shared__ char sm[];
    int m0 = blockIdx.x*64, n0 = blockIdx.y*64;
    float Cr[2][4][4];
    #pragma unroll
    for(int mi=0;mi<2;mi++) for(int ni=0;ni<4;ni++) for(int e=0;e<4;e++) Cr[mi][ni][e]=0.f;
    const size_t ho = (size_t)m0*FOUT, wo = (size_t)n0*(HNUM*HD);
    gemm_bf_main(g_H0+ho,g_H1+ho,FOUT, g_W0[3]+wo,g_W1[3]+wo,HNUM*HD, FOUT, Cr, sm);

    const int tid = threadIdx.x, warp = tid>>5, lane = tid&31;
    const int g = lane>>2, q = lane&3;
    const int wm = (warp>>1)*32, wn = (warp&1)*32;
    #pragma unroll
    for(int mi=0;mi<2;mi++) for(int ni=0;ni<4;ni++){
        int row = m0+wm+mi*16+g, col = n0+wn+ni*8+2*q;
        *(float2*)(Out + (size_t)row*FOUT + col)     = make_float2(Cr[mi][ni][0],Cr[mi][ni][1]);
        *(float2*)(Out + (size_t)(row+8)*FOUT + col) = make_float2(Cr[mi][ni][2],Cr[mi][ni][3]);
    }
}

// ===================== flash (R11-exact): BM=256, BN=64, 16 warps, QK(t+1)-before-PV(t) =====================
#define NT (SEQ/64)
#define OFF_QH 0
#define OFF_QL 32768
#define OFF_K  65536      /* 3 bufs x (Kh 8K | Kl 8K) */
#define OFF_V  114688     /* 3 bufs x 8K (fp16, single plane) */
#define OFF_M  139264     /* int [256][68] single buffer */
#define SMEM_FLASH 208896

__global__ __launch_bounds__(512,1) void flash_bf16_kernel(const int* __restrict__ mask)
{
    extern __shared__ char sm[];
    const uint32_t smb = smem_u32(sm);
    const int tid = threadIdx.x, warp = tid>>5, lane = tid&31;
    const int g = lane>>2, q = lane&3, r0 = warp*16;
    const int h = blockIdx.y, q0 = blockIdx.x*256;

    const bf* Qhg = g_Qh + ((size_t)h*SEQ+q0)*HD;
    const bf* Qlg = g_Ql + ((size_t)h*SEQ+q0)*HD;
    const bf* Khg = g_Kh + (size_t)h*SEQ*HD;
    const bf* Klg = g_Kl + (size_t)h*SEQ*HD;
    const __half* Vhg = g_Vh + (size_t)h*SEQ*HD;
    const int* mg = mask + ((size_t)h*SEQ+q0)*SEQ;
    int* Mi = (int*)(sm + OFF_M);

    const int a_row = (lane&7) + (lane&8);
    const int a_c16 = (lane>>4)&1;
    const int b_row = (lane&7) + ((lane&16)>>1);
    const int b_c16 = (lane>>3)&1;
    const uint32_t a_swz = (uint32_t)(lane&7)<<4;

    #pragma unroll
    for(int i=0;i<8;i++){
        int idx = tid+512*i, half = idx>>11, t = idx&2047, r = t>>3, s = t&7;
        const bf* src = (half? Qlg:Qhg) + (size_t)r*HD + s*8;
        cpa16s(smb + (half?OFF_QL:OFF_QH) + r*128 + ((s*16)^((r&7)<<4)), src);
    }
    auto stageKV = [&](int kt){
        const int k0 = kt*64, buf = kt%3;
        #pragma unroll
        for(int i=0;i<3;i++){
            int idx = tid+512*i, tens = idx>>9, t = idx&511, r = t>>3, s = t&7;
            uint32_t sw = r*128 + ((s*16)^((r&7)<<4));
            if(tens<2) cpa16s(smb + OFF_K + buf*16384 + tens*8192 + sw,
                              (tens? Klg:Khg) + (size_t)(k0+r)*HD + s*8);
            else       cpa16s(smb + OFF_V + buf*8192 + sw, Vhg + (size_t)(k0+r)*HD + s*8);
        }
    };
    auto stageM = [&](int kt){
        const int k0 = kt*64;
        #pragma unroll
        for(int i=0;i<8;i++){
            int idx = tid+512*i, r = idx>>4, s = idx&15;
            cpa16s(smb + OFF_M + (r*68 + s*4)*4, mg + (size_t)r*SEQ + k0 + s*4);
        }
    };

    float S[8][4], O[8][4];
    #pragma unroll
    for(int nt=0;nt<8;nt++) for(int e=0;e<4;e++){ S[nt][e]=0.f; O[nt][e]=0.f; }
    float mr[2]={-1e30f,-1e30f}, lr[2]={0.f,0.f};
    uint32_t P[8][2];

    auto QK = [&](int kt){
        const int buf = kt%3;
        #pragma unroll
        for(int kk4=0;kk4<4;kk4++){
            const uint32_t kkb = kk4*32;
            uint32_t ah[4], al[4];
            uint32_t qa = smb + OFF_QH + (r0+a_row)*128 + ((kkb + a_c16*16) ^ a_swz);
            ldsm4(ah, qa);
            ldsm4(al, qa + 32768);
            #pragma unroll
            for(int ntp=0;ntp<4;ntp++){
                uint32_t bh[4], bl[4];
                uint32_t ka = smb + OFF_K + buf*16384 + (ntp*16+b_row)*128 + ((kkb + b_c16*16) ^ ((uint32_t)(b_row&7)<<4));
                ldsm4(bh, ka);
                ldsm4(bl, ka + 8192);
                mma16(S[2*ntp],   ah, &bh[0]); mma16(S[2*ntp],   ah, &bl[0]); mma16(S[2*ntp],   al, &bh[0]);
                mma16(S[2*ntp+1], ah, &bh[2]); mma16(S[2*ntp+1], ah, &bl[2]); mma16(S[2*ntp+1], al, &bh[2]);
            }
        }
    };
    auto PV = [&](int kt){
        const int buf = kt%3;
        #pragma unroll
        for(int ktp=0;ktp<4;ktp++){
            uint32_t a[4] = { P[2*ktp][0], P[2*ktp][1], P[2*ktp+1][0], P[2*ktp+1][1] };
            #pragma unroll
            for(int np=0;np<4;np++){
                uint32_t vh[4];
                ldsm4t(vh, smb + OFF_V + buf*8192 + (ktp*16 + a_row)*128 + ((np*32 + a_c16*16) ^ a_swz));
                mma16h(O[2*np],   a, &vh[0]);
                mma16h(O[2*np+1], a, &vh[2]);
            }
        }
    };

    stageM(0); stageKV(0); CP_COMMIT();
    stageKV(1); CP_COMMIT();
    CP_WAIT1();
    __syncthreads();
    QK(0);

    for(int t=0;t<NT;t++){
        if(t==NT-1) CP_WAIT0(); else CP_WAIT1();

        const int rA = r0+g, rB = r0+8+g;
        float tmax[2]={-1e30f,-1e30f};
        #pragma unroll
        for(int nt=0;nt<8;nt++){
            int col = nt*8+2*q;
            int2 mA = *(const int2*)(Mi + rA*68 + col);
            int2 mB = *(const int2*)(Mi + rB*68 + col);
            if(!mA.x) S[nt][0]=-1e30f;
            if(!mA.y) S[nt][1]=-1e30f;
            if(!mB.x) S[nt][2]=-1e30f;
            if(!mB.y) S[nt][3]=-1e30f;
            tmax[0]=fmaxf(tmax[0],fmaxf(S[nt][0],S[nt][1]));
            tmax[1]=fmaxf(tmax[1],fmaxf(S[nt][2],S[nt][3]));
        }
        #pragma unroll
        for(int off=1;off<4;off<<=1){
            tmax[0]=fmaxf(tmax[0],__shfl_xor_sync(0xffffffffu,tmax[0],off));
            tmax[1]=fmaxf(tmax[1],__shfl_xor_sync(0xffffffffu,tmax[1],off));
        }
        float corr[2];
        #pragma unroll
        for(int hh=0;hh<2;hh++){
            float mnew = fmaxf(mr[hh], tmax[hh]);
            asm("ex2.approx.ftz.f32 %0,%1;" : "=f"(corr[hh]) : "f"(mr[hh]-mnew));
            mr[hh]=mnew;
        }
        float ts[2]={0.f,0.f};
        #pragma unroll
        for(int nt=0;nt<8;nt++){
            #pragma unroll
            for(int e=0;e<4;e++){
                float v; asm("ex2.approx.ftz.f32 %0,%1;" : "=f"(v) : "f"(S[nt][e]-mr[e>>1]));
                S[nt][e]=v; ts[e>>1]+=v;
            }
        }
        #pragma unroll
        for(int off=1;off<4;off<<=1){
            ts[0]+=__shfl_xor_sync(0xffffffffu,ts[0],off);
            ts[1]+=__shfl_xor_sync(0xffffffffu,ts[1],off);
        }
        lr[0]=lr[0]*corr[0]+ts[0]; lr[1]=lr[1]*corr[1]+ts[1];
        #pragma unroll
        for(int nt=0;nt<8;nt++){
            P[nt][0] = packh2(S[nt][1], S[nt][0]);
            P[nt][1] = packh2(S[nt][3], S[nt][2]);
        }
        #pragma unroll
        for(int nt=0;nt<8;nt++){
            O[nt][0]*=corr[0]; O[nt][1]*=corr[0];
            O[nt][2]*=corr[1]; O[nt][3]*=corr[1];
        }

        __syncthreads();

        if(t+1<NT){
            stageM(t+1); CP_COMMIT();
            CP_WAIT1();
            #pragma unroll
            for(int nt=0;nt<8;nt++) for(int e=0;e<4;e++) S[nt][e]=0.f;
            QK(t+1);
        }
        if(t+2<NT){ stageKV(t+2); CP_COMMIT(); }
        PV(t);
    }

    // ---- epilogue: 2-split Hcat planes ----
    #pragma unroll
    for(int hh=0;hh<2;hh++){
        float inv = 1.f/lr[hh];
        int row = q0 + r0 + hh*8 + g;
        size_t ob = (size_t)row*FOUT + h*HD;
        #pragma unroll
        for(int nt=0;nt<8;nt++){
            int col = nt*8+2*q;
            uint32_t p0,p1;
            split2p(O[nt][2*hh]*inv, O[nt][2*hh+1]*inv, p0, p1);
            *(uint32_t*)(g_H0+ob+col)=p0;
            *(uint32_t*)(g_H1+ob+col)=p1;
        }
    }
}

extern "C" void kernel_launch(void* const* d_in, const int* in_sizes, int n_in,
                              void* d_out, int out_size)
{
    const float* X  = (const float*)d_in[0];
    const int* mask = (const int*)d_in[1];
    const float* WQ = (const float*)d_in[2];
    const float* WK = (const float*)d_in[3];
    const float* WV = (const float*)d_in[4];
    const float* WO = (const float*)d_in[5];
    float* out = (float*)d_out;

    cudaFuncSetAttribute(flash_bf16_kernel, cudaFuncAttributeMaxDynamicSharedMemorySize, SMEM_FLASH);
    cudaFuncSetAttribute(qkv_bf_kernel, cudaFuncAttributeMaxDynamicSharedMemorySize, GP_SM);
    cudaFuncSetAttribute(out_bf_kernel, cudaFuncAttributeMaxDynamicSharedMemorySize, GP_SM);

    splitX_kernel<<<HNUM*SEQ*FIN/1024,256>>>(X);
    splitW_kernel<<<dim3(HNUM*HD*FIN/1024,4),256>>>(WQ,WK,WV,WO);
    qkv_bf_kernel<<<dim3(64,3,8),128,GP_SM>>>();
    flash_bf16_kernel<<<dim3(16,8),512,SMEM_FLASH>>>(mask);
    out_bf_kernel<<<dim3(64,8),128,GP_SM>>>(out);
}

// round 14
// speedup vs baseline: 2.6813x; 1.0078x over previous
#include <cuda_runtime.h>
#include <cuda_bf16.h>
#include <cuda_fp16.h>
#include <cstdint>

#define HNUM 8
#define SEQ  4096
#define FIN  512
#define HD   64
#define FOUT 512
#define S_SCALE 0.18033688011112042f  /* 0.125 * log2(e) */
typedef __nv_bfloat16 bf;

__device__ bf g_X0[HNUM*SEQ*FIN], g_X1[HNUM*SEQ*FIN];
__device__ bf g_W0[4][HNUM*HD*FIN], g_W1[4][HNUM*HD*FIN];
__device__ bf g_Qh[HNUM*SEQ*HD], g_Ql[HNUM*SEQ*HD];
__device__ bf g_Kh[HNUM*SEQ*HD], g_Kl[HNUM*SEQ*HD];
__device__ __half g_Vh[HNUM*SEQ*HD];
__device__ bf g_H0[SEQ*FOUT], g_H1[SEQ*FOUT];

__device__ __forceinline__ uint32_t packbf(float hi, float lo){
    uint32_t d; asm("cvt.rn.bf16x2.f32 %0,%1,%2;" : "=r"(d) : "f"(hi), "f"(lo)); return d;
}
__device__ __forceinline__ uint32_t packh2(float hi, float lo){
    uint32_t d; asm("cvt.rn.f16x2.f32 %0,%1,%2;" : "=r"(d) : "f"(hi), "f"(lo)); return d;
}
__device__ __forceinline__ uint32_t ex2h2(uint32_t a){
    uint32_t d; asm("ex2.approx.f16x2 %0,%1;" : "=r"(d) : "r"(a)); return d;
}
__device__ __forceinline__ void split2p(float v0, float v1, uint32_t& p0, uint32_t& p1){
    p0 = packbf(v1, v0);
    p1 = packbf(v1 - __uint_as_float(p0 & 0xFFFF0000u), v0 - __uint_as_float(p0<<16));
}
__device__ __forceinline__ void cpa16s(uint32_t sa, const void* g){
    asm volatile("cp.async.cg.shared.global [%0],[%1],16;\n" :: "r"(sa),"l"(g));
}
#define CP_COMMIT() asm volatile("cp.async.commit_group;\n")
#define CP_WAIT1()  asm volatile("cp.async.wait_group 1;\n" ::: "memory")
#define CP_WAIT0()  asm volatile("cp.async.wait_group 0;\n" ::: "memory")
__device__ __forceinline__ uint32_t smem_u32(const void* p){
    uint32_t a; asm("{ .reg .u64 t; cvta.to.shared.u64 t, %1; cvt.u32.u64 %0, t; }" : "=r"(a) : "l"(p));
    return a;
}
__device__ __forceinline__ void ldsm4(uint32_t r[4], uint32_t a){
    asm volatile("ldmatrix.sync.aligned.m8n8.x4.shared.b16 {%0,%1,%2,%3},[%4];"
        : "=r"(r[0]),"=r"(r[1]),"=r"(r[2]),"=r"(r[3]) : "r"(a));
}
__device__ __forceinline__ void ldsm4t(uint32_t r[4], uint32_t a){
    asm volatile("ldmatrix.sync.aligned.m8n8.x4.trans.shared.b16 {%0,%1,%2,%3},[%4];"
        : "=r"(r[0]),"=r"(r[1]),"=r"(r[2]),"=r"(r[3]) : "r"(a));
}
__device__ __forceinline__ void mma16(float c[4], const uint32_t a[4], const uint32_t b[2]){
    asm volatile("mma.sync.aligned.m16n8k16.row.col.f32.bf16.bf16.f32 "
        "{%0,%1,%2,%3},{%4,%5,%6,%7},{%8,%9},{%0,%1,%2,%3};\n"
        : "+f"(c[0]),"+f"(c[1]),"+f"(c[2]),"+f"(c[3])
        : "r"(a[0]),"r"(a[1]),"r"(a[2]),"r"(a[3]),"r"(b[0]),"r"(b[1]));
}
__device__ __forceinline__ void mma16h(float c[4], const uint32_t a[4], const uint32_t b[2]){
    asm volatile("mma.sync.aligned.m16n8k16.row.col.f32.f16.f16.f32 "
        "{%0,%1,%2,%3},{%4,%5,%6,%7},{%8,%9},{%0,%1,%2,%3};\n"
        : "+f"(c[0]),"+f"(c[1]),"+f"(c[2]),"+f"(c[3])
        : "r"(a[0]),"r"(a[1]),"r"(a[2]),"r"(a[3]),"r"(b[0]),"r"(b[1]));
}

// ===================== split kernels (2 planes) =====================
__global__ __launch_bounds__(256) void splitX_kernel(const float* __restrict__ X)
{
    size_t i = ((size_t)blockIdx.x*256 + threadIdx.x)*4;
    float4 v = *(const float4*)(X+i);
    uint32_t a0,a1,b0,b1;
    split2p(v.x,v.y,a0,a1); split2p(v.z,v.w,b0,b1);
    *(uint32_t*)(g_X0+i)=a0; *(uint32_t*)(g_X0+i+2)=b0;
    *(uint32_t*)(g_X1+i)=a1; *(uint32_t*)(g_X1+i+2)=b1;
}
__global__ __launch_bounds__(256) void splitW_kernel(const float* __restrict__ WQ,
    const float* __restrict__ WK, const float* __restrict__ WV, const float* __restrict__ WO)
{
    int m = blockIdx.y;
    const float* src = (m==0)?WQ:(m==1)?WK:(m==2)?WV:WO;
    size_t i = ((size_t)blockIdx.x*256 + threadIdx.x)*4;
    float4 v = *(const float4*)(src+i);
    uint32_t a0,a1,b0,b1;
    split2p(v.x,v.y,a0,a1); split2p(v.z,v.w,b0,b1);
    *(uint32_t*)(g_W0[m]+i)=a0; *(uint32_t*)(g_W0[m]+i+2)=b0;
    *(uint32_t*)(g_W1[m]+i)=a1; *(uint32_t*)(g_W1[m]+i+2)=b1;
}

// ===================== bf16 2-plane 3-product GEMM core (double-buffered) =====================
#define GP_SM 65536
__device__ __forceinline__ void gemm_bf_main(
    const bf* A0,const bf* A1,int lda,
    const bf* B0,const bf* B1,int ldb,
    int K, float Cr[2][4][4], char* sm)
{
    const uint32_t smb = smem_u32(sm);
    const int tid = threadIdx.x, warp = tid>>5, lane = tid&31;
    const int wm = (warp>>1)*32, wn = (warp&1)*32;
    const int a_row = (lane&7) + (lane&8);
    const int a_c16 = (lane>>4)&1;
    const int b_row = (lane&7) + ((lane&16)>>1);
    const int b_c16 = (lane>>3)&1;
    const bf* Ap[2] = {A0,A1};
    const bf* Bp[2] = {B0,B1};
    const int PA[3] = {0,0,1};
    const int PB[3] = {0,1,0};

    auto stage = [&](int buf, int k0){
        #pragma unroll
        for(int i=0;i<16;i++){
            int idx = tid+128*i, side = idx>>10, p = (idx>>9)&1, t = idx&511, r = t>>3, s = t&7;
            uint32_t off = buf*32768 + side*16384 + p*8192 + r*128 + ((s*16)^((r&7)<<4));
            const bf* src = side? Bp[p] : Ap[p];
            int ld = side? ldb : lda;
            cpa16s(smb + off, src + (size_t)r*ld + k0 + s*8);
        }
    };
    stage(0,0); CP_COMMIT();
    const int nc = K/64;
    for(int c=0;c<nc;c++){
        const int buf = c&1;
        if(c+1<nc){ stage(buf^1, (c+1)*64); CP_COMMIT(); CP_WAIT1(); }
        else CP_WAIT0();
        __syncthreads();
        const uint32_t bb = smb + buf*32768;
        #pragma unroll
        for(int k16=0;k16<4;k16++){
            uint32_t aF[2][2][4], bF[2][2][4];
            #pragma unroll
            for(int p=0;p<2;p++){
                #pragma unroll
                for(int mi=0;mi<2;mi++)
                    ldsm4(aF[p][mi], bb + p*8192 + (wm+mi*16+a_row)*128 + ((k16*32 + a_c16*16)^((a_row&7)<<4)));
                #pragma unroll
                for(int nj=0;nj<2;nj++)
                    ldsm4(bF[p][nj], bb + 16384 + p*8192 + (wn+nj*16+b_row)*128 + ((k16*32 + b_c16*16)^((b_row&7)<<4)));
            }
            #pragma unroll
            for(int cc=0;cc<3;cc++){
                #pragma unroll
                for(int mi=0;mi<2;mi++){
                    #pragma unroll
                    for(int nj=0;nj<2;nj++){
                        mma16(Cr[mi][2*nj],   aF[PA[cc]][mi], &bF[PB[cc]][nj][0]);
                        mma16(Cr[mi][2*nj+1], aF[PA[cc]][mi], &bF[PB[cc]][nj][2]);
                    }
                }
            }
        }
        __syncthreads();
    }
}

// qkv: C -> bf16 hi/lo for Q(scaled)/K, fp16 single plane for V
__global__ __launch_bounds__(128) void qkv_bf_kernel()
{
    extern __shared__ char sm[];
    int h = blockIdx.z, p = blockIdx.y, m0 = blockIdx.x*64;
    float Cr[2][4][4];
    #pragma unroll
    for(int mi=0;mi<2;mi++) for(int ni=0;ni<4;ni++) for(int e=0;e<4;e++) Cr[mi][ni][e]=0.f;
    const size_t xo = ((size_t)h*SEQ+m0)*FIN, wo = (size_t)h*HD*FIN;
    gemm_bf_main(g_X0+xo,g_X1+xo,FIN, g_W0[p]+wo,g_W1[p]+wo,FIN, FIN, Cr, sm);

    const float sc = (p==0)? S_SCALE : 1.0f;
    const int tid = threadIdx.x, warp = tid>>5, lane = tid&31;
    const int g = lane>>2, q = lane&3;
    const int wm = (warp>>1)*32, wn = (warp&1)*32;
    #pragma unroll
    for(int mi=0;mi<2;mi++) for(int ni=0;ni<4;ni++){
        int row = wm+mi*16+g, col = wn+ni*8+2*q;
        size_t o = ((size_t)h*SEQ + m0 + row)*HD + col;
        uint32_t p0,p1;
        if(p==2){
            *(uint32_t*)(g_Vh+o)      = packh2(Cr[mi][ni][1], Cr[mi][ni][0]);
            *(uint32_t*)(g_Vh+o+8*HD) = packh2(Cr[mi][ni][3], Cr[mi][ni][2]);
        }else{
            bf *H = (p==0)?g_Qh:g_Kh;
            bf *L = (p==0)?g_Ql:g_Kl;
            split2p(Cr[mi][ni][0]*sc, Cr[mi][ni][1]*sc, p0, p1);
            *(uint32_t*)(H+o)=p0; *(uint32_t*)(L+o)=p1;
            split2p(Cr[mi][ni][2]*sc, Cr[mi][ni][3]*sc, p0, p1);
            *(uint32_t*)(H+o+8*HD)=p0; *(uint32_t*)(L+o+8*HD)=p1;
        }
    }
}

__global__ __launch_bounds__(128) void out_bf_kernel(float* __restrict__ Out)
{
    extern __shared__ char sm[];
    int m0 = blockIdx.x*64, n0 = blockIdx.y*64;
    float Cr[2][4][4];
    #pragma unroll
    for(int mi=0;mi<2;mi++) for(int ni=0;ni<4;ni++) for(int e=0;e<4;e++) Cr[mi][ni][e]=0.f;
    const size_t ho = (size_t)m0*FOUT, wo = (size_t)n0*(HNUM*HD);
    gemm_bf_main(g_H0+ho,g_H1+ho,FOUT, g_W0[3]+wo,g_W1[3]+wo,HNUM*HD, FOUT, Cr, sm);

    const int tid = threadIdx.x, warp = tid>>5, lane = tid&31;
    const int g = lane>>2, q = lane&3;
    const int wm = (warp>>1)*32, wn = (warp&1)*32;
    #pragma unroll
    for(int mi=0;mi<2;mi++) for(int ni=0;ni<4;ni++){
        int row = m0+wm+mi*16+g, col = n0+wn+ni*8+2*q;
        *(float2*)(Out + (size_t)row*FOUT + col)     = make_float2(Cr[mi][ni][0],Cr[mi][ni][1]);
        *(float2*)(Out + (size_t)(row+8)*FOUT + col) = make_float2(Cr[mi][ni][2],Cr[mi][ni][3]);
    }
}

// ===================== flash: BM=256, BN=64, 16 warps, f16x2-exp + sum-via-mma =====================
#define NT (SEQ/64)
#define OFF_QH 0
#define OFF_QL 32768
#define OFF_K  65536      /* 3 bufs x (Kh 8K | Kl 8K) */
#define OFF_V  114688     /* 3 bufs x 8K (fp16, single plane) */
#define OFF_M  139264     /* int [256][68] single buffer */
#define SMEM_FLASH 208896

__global__ __launch_bounds__(512,1) void flash_bf16_kernel(const int* __restrict__ mask)
{
    extern __shared__ char sm[];
    const uint32_t smb = smem_u32(sm);
    const int tid = threadIdx.x, warp = tid>>5, lane = tid&31;
    const int g = lane>>2, q = lane&3, r0 = warp*16;
    const int h = blockIdx.y, q0 = blockIdx.x*256;

    const bf* Qhg = g_Qh + ((size_t)h*SEQ+q0)*HD;
    const bf* Qlg = g_Ql + ((size_t)h*SEQ+q0)*HD;
    const bf* Khg = g_Kh + (size_t)h*SEQ*HD;
    const bf* Klg = g_Kl + (size_t)h*SEQ*HD;
    const __half* Vhg = g_Vh + (size_t)h*SEQ*HD;
    const int* mg = mask + ((size_t)h*SEQ+q0)*SEQ;
    int* Mi = (int*)(sm + OFF_M);

    const int a_row = (lane&7) + (lane&8);
    const int a_c16 = (lane>>4)&1;
    const int b_row = (lane&7) + ((lane&16)>>1);
    const int b_c16 = (lane>>3)&1;
    const uint32_t a_swz = (uint32_t)(lane&7)<<4;
    const uint32_t ONES2 = 0x3C003C00u;           // fp16 {1,1}
    const uint32_t bones[2] = {ONES2, ONES2};

    #pragma unroll
    for(int i=0;i<8;i++){
        int idx = tid+512*i, half = idx>>11, t = idx&2047, r = t>>3, s = t&7;
        const bf* src = (half? Qlg:Qhg) + (size_t)r*HD + s*8;
        cpa16s(smb + (half?OFF_QL:OFF_QH) + r*128 + ((s*16)^((r&7)<<4)), src);
    }
    auto stageKV = [&](int kt){
        const int k0 = kt*64, buf = kt%3;
        #pragma unroll
        for(int i=0;i<3;i++){
            int idx = tid+512*i, tens = idx>>9, t = idx&511, r = t>>3, s = t&7;
            uint32_t sw = r*128 + ((s*16)^((r&7)<<4));
            if(tens<2) cpa16s(smb + OFF_K + buf*16384 + tens*8192 + sw,
                              (tens? Klg:Khg) + (size_t)(k0+r)*HD + s*8);
            else       cpa16s(smb + OFF_V + buf*8192 + sw, Vhg + (size_t)(k0+r)*HD + s*8);
        }
    };
    auto stageM = [&](int kt){
        const int k0 = kt*64;
        #pragma unroll
        for(int i=0;i<8;i++){
            int idx = tid+512*i, r = idx>>4, s = idx&15;
            cpa16s(smb + OFF_M + (r*68 + s*4)*4, mg + (size_t)r*SEQ + k0 + s*4);
        }
    };

    float S[8][4], O[8][4], Osum[4];
    #pragma unroll
    for(int nt=0;nt<8;nt++) for(int e=0;e<4;e++){ S[nt][e]=0.f; O[nt][e]=0.f; }
    #pragma unroll
    for(int e=0;e<4;e++) Osum[e]=0.f;
    float mr[2]={-1e30f,-1e30f};
    uint32_t P[8][2];

    auto QK = [&](int kt){
        const int buf = kt%3;
        #pragma unroll
        for(int kk4=0;kk4<4;kk4++){
            const uint32_t kkb = kk4*32;
            uint32_t ah[4], al[4];
            uint32_t qa = smb + OFF_QH + (r0+a_row)*128 + ((kkb + a_c16*16) ^ a_swz);
            ldsm4(ah, qa);
            ldsm4(al, qa + 32768);
            #pragma unroll
            for(int ntp=0;ntp<4;ntp++){
                uint32_t bh[4], bl[4];
                uint32_t ka = smb + OFF_K + buf*16384 + (ntp*16+b_row)*128 + ((kkb + b_c16*16) ^ ((uint32_t)(b_row&7)<<4));
                ldsm4(bh, ka);
                ldsm4(bl, ka + 8192);
                mma16(S[2*ntp],   ah, &bh[0]); mma16(S[2*ntp],   ah, &bl[0]); mma16(S[2*ntp],   al, &bh[0]);
                mma16(S[2*ntp+1], ah, &bh[2]); mma16(S[2*ntp+1], ah, &bl[2]); mma16(S[2*ntp+1], al, &bh[2]);
            }
        }
    };
    auto PV = [&](int kt){
        const int buf = kt%3;
        #pragma unroll
        for(int ktp=0;ktp<4;ktp++){
            uint32_t a[4] = { P[2*ktp][0], P[2*ktp][1], P[2*ktp+1][0], P[2*ktp+1][1] };
            mma16h(Osum, a, bones);                    // row-sum column (V==1)
            #pragma unroll
            for(int np=0;np<4;np++){
                uint32_t vh[4];
                ldsm4t(vh, smb + OFF_V + buf*8192 + (ktp*16 + a_row)*128 + ((np*32 + a_c16*16) ^ a_swz));
                mma16h(O[2*np],   a, &vh[0]);
                mma16h(O[2*np+1], a, &vh[2]);
            }
        }
    };

    stageM(0); stageKV(0); CP_COMMIT();
    stageKV(1); CP_COMMIT();
    CP_WAIT1();
    __syncthreads();
    QK(0);

    for(int t=0;t<NT;t++){
        if(t==NT-1) CP_WAIT0(); else CP_WAIT1();

        // ---- softmax(t): mask, max, f16x2 exp ----
        const int rA = r0+g, rB = r0+8+g;
        float tmax[2]={-1e30f,-1e30f};
        #pragma unroll
        for(int nt=0;nt<8;nt++){
            int col = nt*8+2*q;
            int2 mA = *(const int2*)(Mi + rA*68 + col);
            int2 mB = *(const int2*)(Mi + rB*68 + col);
            if(!mA.x) S[nt][0]=-1e30f;
            if(!mA.y) S[nt][1]=-1e30f;
            if(!mB.x) S[nt][2]=-1e30f;
            if(!mB.y) S[nt][3]=-1e30f;
            tmax[0]=fmaxf(tmax[0],fmaxf(S[nt][0],S[nt][1]));
            tmax[1]=fmaxf(tmax[1],fmaxf(S[nt][2],S[nt][3]));
        }
        #pragma unroll
        for(int off=1;off<4;off<<=1){
            tmax[0]=fmaxf(tmax[0],__shfl_xor_sync(0xffffffffu,tmax[0],off));
            tmax[1]=fmaxf(tmax[1],__shfl_xor_sync(0xffffffffu,tmax[1],off));
        }
        float corr[2];
        #pragma unroll
        for(int hh=0;hh<2;hh++){
            float mnew = fmaxf(mr[hh], tmax[hh]);
            asm("ex2.approx.ftz.f32 %0,%1;" : "=f"(corr[hh]) : "f"(mr[hh]-mnew));
            mr[hh]=mnew;
        }
        #pragma unroll
        for(int nt=0;nt<8;nt++){
            P[nt][0] = ex2h2(packh2(S[nt][1]-mr[0], S[nt][0]-mr[0]));
            P[nt][1] = ex2h2(packh2(S[nt][3]-mr[1], S[nt][2]-mr[1]));
        }
        #pragma unroll
        for(int nt=0;nt<8;nt++){
            O[nt][0]*=corr[0]; O[nt][1]*=corr[0];
            O[nt][2]*=corr[1]; O[nt][3]*=corr[1];
        }
        Osum[0]*=corr[0]; Osum[1]*=corr[0];
        Osum[2]*=corr[1]; Osum[3]*=corr[1];

        __syncthreads();

        if(t+1<NT){
            stageM(t+1); CP_COMMIT();
            CP_WAIT1();
            #pragma unroll
            for(int nt=0;nt<8;nt++) for(int e=0;e<4;e++) S[nt][e]=0.f;
            QK(t+1);
        }
        if(t+2<NT){ stageKV(t+2); CP_COMMIT(); }
        PV(t);
    }

    // ---- epilogue: 2-split Hcat planes, normalize by Osum ----
    #pragma unroll
    for(int hh=0;hh<2;hh++){
        float inv = 1.f/Osum[2*hh];
        int row = q0 + r0 + hh*8 + g;
        size_t ob = (size_t)row*FOUT + h*HD;
        #pragma unroll
        for(int nt=0;nt<8;nt++){
            int col = nt*8+2*q;
            uint32_t p0,p1;
            split2p(O[nt][2*hh]*inv, O[nt][2*hh+1]*inv, p0, p1);
            *(uint32_t*)(g_H0+ob+col)=p0;
            *(uint32_t*)(g_H1+ob+col)=p1;
        }
    }
}

extern "C" void kernel_launch(void* const* d_in, const int* in_sizes, int n_in,
                              void* d_out, int out_size)
{
    const float* X  = (const float*)d_in[0];
    const int* mask = (const int*)d_in[1];
    const float* WQ = (const float*)d_in[2];
    const float* WK = (const float*)d_in[3];
    const float* WV = (const float*)d_in[4];
    const float* WO = (const float*)d_in[5];
    float* out = (float*)d_out;

    cudaFuncSetAttribute(flash_bf16_kernel, cudaFuncAttributeMaxDynamicSharedMemorySize, SMEM_FLASH);
    cudaFuncSetAttribute(qkv_bf_kernel, cudaFuncAttributeMaxDynamicSharedMemorySize, GP_SM);
    cudaFuncSetAttribute(out_bf_kernel, cudaFuncAttributeMaxDynamicSharedMemorySize, GP_SM);

    splitX_kernel<<<HNUM*SEQ*FIN/1024,256>>>(X);
    splitW_kernel<<<dim3(HNUM*HD*FIN/1024,4),256>>>(WQ,WK,WV,WO);
    qkv_bf_kernel<<<dim3(64,3,8),128,GP_SM>>>();
    flash_bf16_kernel<<<dim3(16,8),512,SMEM_FLASH>>>(mask);
    out_bf_kernel<<<dim3(64,8),128,GP_SM>>>(out);
}